// round 4
// baseline (speedup 1.0000x reference)
#include <cuda_runtime.h>
#include <math_constants.h>
#include <cstdint>

#define Bb   16
#define Nn   2048
#define Cc   10
#define KK   16
#define BNT  (Bb*Nn)        // 32768 nodes
#define EDG  (BNT*KK)       // 524288 edges

// ---------------- scratch (device globals: no allocation allowed) ----------
__device__ int   g_nbr[EDG];        // forward: node -> its 16 nearest (global idx)
__device__ int   g_deg[BNT];        // in-degree of reverse graph
__device__ int   g_off[BNT];        // CSR offsets (exclusive scan of deg)
__device__ int   g_cur[BNT];        // fill cursors
__device__ int   g_rev[EDG];        // reverse adjacency lists
__device__ float g_h [BNT*128];
__device__ float g_hb[BNT*128];
__device__ float g_y [BNT*256];     // [y_rel | y_root]

// ---------------- utility ----------------
__global__ void clear_deg_kernel() {
    int i = blockIdx.x * blockDim.x + threadIdx.x;
    if (i < BNT) g_deg[i] = 0;
}

// ---------------- kNN: one lane per query point -------------------------
// Block = 128 threads = 128 consecutive points of one batch.
// Candidate rows are loaded uniformly (warp-broadcast) as float4 groups of 4 points.
__global__ void knn_kernel(const float* __restrict__ x) {
    __shared__ float sd[128 * 17];
    __shared__ int   si[128 * 17];
    int t    = threadIdx.x;
    int node = blockIdx.x * 128 + t;        // global node id
    int b    = node >> 11;                  // /2048
    int i    = node & 2047;
    const float*  xb  = x + (size_t)b * Nn * Cc;
    const float4* xb4 = (const float4*)xb;  // batch base is 16B aligned

    float xi[Cc];
#pragma unroll
    for (int c = 0; c < Cc; c++) xi[c] = xb[i * Cc + c];

    float* sdt = sd + t * 17;
    int*   sit = si + t * 17;
#pragma unroll
    for (int r = 0; r < KK; r++) { sdt[r] = CUDART_INF_F; sit[r] = 0; }
    float cut = CUDART_INF_F;

    for (int j0 = 0; j0 < Nn; j0 += 4) {
        float v[40];
#pragma unroll
        for (int q = 0; q < 10; q++) {
            float4 t4 = xb4[(j0 * 10) / 4 + q];
            v[q*4+0] = t4.x; v[q*4+1] = t4.y; v[q*4+2] = t4.z; v[q*4+3] = t4.w;
        }
#pragma unroll
        for (int jj = 0; jj < 4; jj++) {
            int j = j0 + jj;
            float d2 = 0.f;
#pragma unroll
            for (int c = 0; c < Cc; c++) {
                float df = xi[c] - v[jj * 10 + c];
                d2 = fmaf(df, df, d2);
            }
            if (j != i && d2 < cut) {
                int p = KK - 1;
                while (p > 0 && sdt[p-1] > d2) {
                    sdt[p] = sdt[p-1]; sit[p] = sit[p-1]; p--;
                }
                sdt[p] = d2; sit[p] = j;
                cut = sdt[KK - 1];
            }
        }
    }
    int base = node * KK;
#pragma unroll
    for (int r = 0; r < KK; r++) {
        int nb = (b << 11) + sit[r];
        g_nbr[base + r] = nb;
        atomicAdd(&g_deg[nb], 1);
    }
}

// ---------------- exclusive scan of deg (single block) -------------------
__global__ void scan_kernel() {
    __shared__ int sh[1024];
    __shared__ int carry;
    int t = threadIdx.x;
    if (t == 0) carry = 0;
    __syncthreads();
    for (int c = 0; c < BNT / 1024; c++) {
        int idx = c * 1024 + t;
        int v = g_deg[idx];
        sh[t] = v;
        __syncthreads();
        for (int off = 1; off < 1024; off <<= 1) {
            int add = (t >= off) ? sh[t - off] : 0;
            __syncthreads();
            sh[t] += add;
            __syncthreads();
        }
        int excl = sh[t] - v + carry;
        g_off[idx] = excl;
        g_cur[idx] = excl;
        __syncthreads();
        if (t == 1023) carry = carry + sh[1023];
        __syncthreads();
    }
}

// ---------------- fill reverse adjacency ---------------------------------
__global__ void fill_kernel() {
    int e = blockIdx.x * blockDim.x + threadIdx.x;
    if (e >= EDG) return;
    int i = e >> 4;                 // source node
    int v = g_nbr[e];               // target node
    int pos = atomicAdd(&g_cur[v], 1);
    g_rev[pos] = i;
}

// ---------------- GEMM: Y[M x 2P] = A[M x Kd] @ [w_rel | w_root] ----------
// 128x128 block tile, BK=8, 256 threads, 8x8 micro-tile.
__global__ void gemm_cat_kernel(const float* __restrict__ A,
                                const float* __restrict__ wr,
                                const float* __restrict__ wo,
                                float* __restrict__ Y,
                                int M, int Kd, int P) {
    __shared__ __align__(16) float As[8][128];
    __shared__ __align__(16) float Bs[8][128];
    int NN = 2 * P;
    int bm = blockIdx.y * 128;
    int bn = blockIdx.x * 128;
    int tid = threadIdx.x;
    int tx = tid & 15, ty = tid >> 4;

    float acc[8][8];
#pragma unroll
    for (int a = 0; a < 8; a++)
#pragma unroll
        for (int c = 0; c < 8; c++) acc[a][c] = 0.f;

    int a_m = tid >> 1;             // 0..127
    int a_k = (tid & 1) * 4;        // 0 or 4
    int b_k = tid >> 5;             // 0..7
    int b_n = (tid & 31) * 4;       // 0..124

    bool vec_a = ((Kd & 7) == 0);

    for (int k0 = 0; k0 < Kd; k0 += 8) {
        // ---- load A tile transposed ----
        if (vec_a) {
            float4 v = *(const float4*)&A[(size_t)(bm + a_m) * Kd + k0 + a_k];
            As[a_k+0][a_m] = v.x; As[a_k+1][a_m] = v.y;
            As[a_k+2][a_m] = v.z; As[a_k+3][a_m] = v.w;
        } else {
#pragma unroll
            for (int q = 0; q < 4; q++) {
                int kk = k0 + a_k + q;
                As[a_k+q][a_m] = (kk < Kd) ? A[(size_t)(bm + a_m) * Kd + kk] : 0.f;
            }
        }
        // ---- load W tile (concat of wr|wo) ----
        {
            int kk = k0 + b_k;
            float4 v = make_float4(0.f, 0.f, 0.f, 0.f);
            if (kk < Kd) {
                int n = bn + b_n;
                const float* src = (n < P) ? &wr[(size_t)kk * P + n]
                                           : &wo[(size_t)kk * P + (n - P)];
                v = *(const float4*)src;
            }
            *(float4*)&Bs[b_k][b_n] = v;
        }
        __syncthreads();
#pragma unroll
        for (int kk = 0; kk < 8; kk++) {
            float af[8], bf[8];
            *(float4*)&af[0] = *(const float4*)&As[kk][ty * 8];
            *(float4*)&af[4] = *(const float4*)&As[kk][ty * 8 + 4];
            *(float4*)&bf[0] = *(const float4*)&Bs[kk][tx * 8];
            *(float4*)&bf[4] = *(const float4*)&Bs[kk][tx * 8 + 4];
#pragma unroll
            for (int ii = 0; ii < 8; ii++)
#pragma unroll
                for (int jj = 0; jj < 8; jj++)
                    acc[ii][jj] = fmaf(af[ii], bf[jj], acc[ii][jj]);
        }
        __syncthreads();
    }
#pragma unroll
    for (int ii = 0; ii < 8; ii++) {
        size_t row = (size_t)(bm + ty * 8 + ii) * NN + bn + tx * 8;
        *(float4*)&Y[row]     = make_float4(acc[ii][0], acc[ii][1], acc[ii][2], acc[ii][3]);
        *(float4*)&Y[row + 4] = make_float4(acc[ii][4], acc[ii][5], acc[ii][6], acc[ii][7]);
    }
}

// ---------------- combine: h_out[v] = relu( sum_rev y_rel[u] + y_root[v] + b )
__global__ void combine_kernel(const float* __restrict__ Y,
                               const float* __restrict__ bias,
                               float* __restrict__ Hout,
                               int P, int do_relu) {
    int v = blockIdx.x;
    int t = threadIdx.x;            // 0..P-1
    int NN = 2 * P;
    int s = g_off[v];
    int e = s + g_deg[v];
    float acc = 0.f;
    for (int q = s; q < e; q++) {
        int u = g_rev[q];
        acc += Y[(size_t)u * NN + t];
    }
    float o = acc + Y[(size_t)v * NN + P + t] + bias[t];
    if (do_relu) o = fmaxf(o, 0.f);
    Hout[(size_t)v * P + t] = o;
}

// ---------------- final: out[b,i,j] = dot(H[b,i,:], H[b,j,:]), K=64 --------
__global__ void final_syrk_kernel(const float* __restrict__ H,
                                  float* __restrict__ out) {
    __shared__ __align__(16) float As[32][128];
    __shared__ __align__(16) float Bs[32][128];
    int b  = blockIdx.z;
    int i0 = blockIdx.y * 128;
    int j0 = blockIdx.x * 128;
    const float* Hb = H + (size_t)b * Nn * 64;
    int tid = threadIdx.x;
    int tx = tid & 15, ty = tid >> 4;

    float acc[8][8];
#pragma unroll
    for (int a = 0; a < 8; a++)
#pragma unroll
        for (int c = 0; c < 8; c++) acc[a][c] = 0.f;

    for (int k0 = 0; k0 < 64; k0 += 32) {
#pragma unroll
        for (int q = 0; q < 4; q++) {
            int f  = tid * 4 + q;       // 0..1023 float4 slots
            int r  = f >> 3;            // row 0..127
            int c4 = (f & 7) * 4;       // k-offset 0..28
            float4 va = *(const float4*)&Hb[(size_t)(i0 + r) * 64 + k0 + c4];
            As[c4+0][r] = va.x; As[c4+1][r] = va.y; As[c4+2][r] = va.z; As[c4+3][r] = va.w;
            float4 vb = *(const float4*)&Hb[(size_t)(j0 + r) * 64 + k0 + c4];
            Bs[c4+0][r] = vb.x; Bs[c4+1][r] = vb.y; Bs[c4+2][r] = vb.z; Bs[c4+3][r] = vb.w;
        }
        __syncthreads();
#pragma unroll
        for (int kk = 0; kk < 32; kk++) {
            float af[8], bf[8];
            *(float4*)&af[0] = *(const float4*)&As[kk][ty * 8];
            *(float4*)&af[4] = *(const float4*)&As[kk][ty * 8 + 4];
            *(float4*)&bf[0] = *(const float4*)&Bs[kk][tx * 8];
            *(float4*)&bf[4] = *(const float4*)&Bs[kk][tx * 8 + 4];
#pragma unroll
            for (int ii = 0; ii < 8; ii++)
#pragma unroll
                for (int jj = 0; jj < 8; jj++)
                    acc[ii][jj] = fmaf(af[ii], bf[jj], acc[ii][jj]);
        }
        __syncthreads();
    }
    float* ob = out + (size_t)b * Nn * Nn;
#pragma unroll
    for (int ii = 0; ii < 8; ii++) {
        size_t row = (size_t)(i0 + ty * 8 + ii) * Nn + j0 + tx * 8;
        *(float4*)&ob[row]     = make_float4(acc[ii][0], acc[ii][1], acc[ii][2], acc[ii][3]);
        *(float4*)&ob[row + 4] = make_float4(acc[ii][4], acc[ii][5], acc[ii][6], acc[ii][7]);
    }
}

// ---------------- launch ---------------------------------------------------
extern "C" void kernel_launch(void* const* d_in, const int* in_sizes, int n_in,
                              void* d_out, int out_size) {
    const float* x   = (const float*)d_in[0];
    const float* wr0 = (const float*)d_in[1];
    const float* wo0 = (const float*)d_in[2];
    const float* bb0 = (const float*)d_in[3];
    const float* wr1 = (const float*)d_in[4];
    const float* wo1 = (const float*)d_in[5];
    const float* bb1 = (const float*)d_in[6];
    const float* wr2 = (const float*)d_in[7];
    const float* wo2 = (const float*)d_in[8];
    const float* bb2 = (const float*)d_in[9];
    const float* wr3 = (const float*)d_in[10];
    const float* wo3 = (const float*)d_in[11];
    const float* bb3 = (const float*)d_in[12];
    float* out = (float*)d_out;

    float *hA, *hB, *Y;
    cudaGetSymbolAddress((void**)&hA, g_h);
    cudaGetSymbolAddress((void**)&hB, g_hb);
    cudaGetSymbolAddress((void**)&Y,  g_y);

    // graph construction
    clear_deg_kernel<<<(BNT + 255) / 256, 256>>>();
    knn_kernel<<<BNT / 128, 128>>>(x);
    scan_kernel<<<1, 1024>>>();
    fill_kernel<<<(EDG + 255) / 256, 256>>>();

    // layer 0: x(K=10) -> 128
    gemm_cat_kernel<<<dim3(2, BNT / 128), 256>>>(x, wr0, wo0, Y, BNT, 10, 128);
    combine_kernel<<<BNT, 128>>>(Y, bb0, hA, 128, 1);
    // layer 1: 128 -> 128
    gemm_cat_kernel<<<dim3(2, BNT / 128), 256>>>(hA, wr1, wo1, Y, BNT, 128, 128);
    combine_kernel<<<BNT, 128>>>(Y, bb1, hB, 128, 1);
    // layer 2: 128 -> 128
    gemm_cat_kernel<<<dim3(2, BNT / 128), 256>>>(hB, wr2, wo2, Y, BNT, 128, 128);
    combine_kernel<<<BNT, 128>>>(Y, bb2, hA, 128, 1);
    // layer 3: 128 -> 64 (no relu)
    gemm_cat_kernel<<<dim3(1, BNT / 128), 256>>>(hA, wr3, wo3, Y, BNT, 128, 64);
    combine_kernel<<<BNT, 64>>>(Y, bb3, hB, 64, 0);

    // final bilinear: out[b,i,j] = <h_i, h_j>
    final_syrk_kernel<<<dim3(Nn / 128, Nn / 128, Bb), 256>>>(hB, out);
}

// round 8
// speedup vs baseline: 1.5679x; 1.5679x over previous
#include <cuda_runtime.h>
#include <math_constants.h>
#include <cstdint>

#define Bb   16
#define Nn   2048
#define Cc   10
#define KK   16
#define BNT  (Bb*Nn)        // 32768 nodes
#define EDG  (BNT*KK)       // 524288 edges

// ---------------- scratch (device globals: no allocation allowed) ----------
__device__ int   g_nbr[EDG];
__device__ int   g_deg[BNT];
__device__ int   g_off[BNT];
__device__ int   g_cur[BNT];
__device__ int   g_rev[EDG];
__device__ float g_h [BNT*128];
__device__ float g_hb[BNT*128];
__device__ float g_y [BNT*256];     // [y_rel | y_root]

__global__ void clear_deg_kernel() {
    int i = blockIdx.x * blockDim.x + threadIdx.x;
    if (i < BNT) g_deg[i] = 0;
}

// ---------------- kNN v2: norm trick + unsorted k-best (replace-max) -------
// Block = 128 threads = 128 consecutive query points of one batch.
__global__ void knn_kernel(const float* __restrict__ x) {
    __shared__ float sn[Nn];          // candidate squared norms
    __shared__ float sd[KK][128];     // per-thread k-best distances ([r][t]: bank=t, conflict-free)
    __shared__ int   si[KK][128];
    int t    = threadIdx.x;
    int node = blockIdx.x * 128 + t;
    int b    = node >> 11;
    int i    = node & 2047;
    const float*  xb  = x + (size_t)b * Nn * Cc;
    const float4* xb4 = (const float4*)xb;

    // cooperative norm precompute
    for (int j = t; j < Nn; j += 128) {
        float s = 0.f;
#pragma unroll
        for (int c = 0; c < Cc; c++) { float v = xb[j * Cc + c]; s = fmaf(v, v, s); }
        sn[j] = s;
    }
    float xi[Cc];
#pragma unroll
    for (int c = 0; c < Cc; c++) xi[c] = xb[i * Cc + c];
#pragma unroll
    for (int r = 0; r < KK; r++) { sd[r][t] = CUDART_INF_F; si[r][t] = 0; }
    __syncthreads();
    float x2i = sn[i];

    float cut = CUDART_INF_F;
    int   cutpos = 0;

    for (int j0 = 0; j0 < Nn; j0 += 4) {
        float v[40];
#pragma unroll
        for (int q = 0; q < 10; q++) {
            float4 t4 = xb4[(j0 * 10) / 4 + q];
            v[q*4+0] = t4.x; v[q*4+1] = t4.y; v[q*4+2] = t4.z; v[q*4+3] = t4.w;
        }
#pragma unroll
        for (int jj = 0; jj < 4; jj++) {
            int j = j0 + jj;
            float dot = 0.f;
#pragma unroll
            for (int c = 0; c < Cc; c++) dot = fmaf(xi[c], v[jj * 10 + c], dot);
            float d2 = fmaf(-2.f, dot, x2i + sn[j]);
            if (j != i && d2 < cut) {
                sd[cutpos][t] = d2; si[cutpos][t] = j;
                // rescan for new max (unsorted set; scatter-add is order-invariant)
                float m = sd[0][t]; int mp = 0;
#pragma unroll
                for (int r = 1; r < KK; r++) {
                    float dr = sd[r][t];
                    if (dr > m) { m = dr; mp = r; }
                }
                cut = m; cutpos = mp;
            }
        }
    }
    int base = node * KK;
#pragma unroll
    for (int r = 0; r < KK; r++) {
        int nb = (b << 11) + si[r][t];
        g_nbr[base + r] = nb;
        atomicAdd(&g_deg[nb], 1);
    }
}

// ---------------- exclusive scan of deg (single block) ----------------------
__global__ void scan_kernel() {
    __shared__ int sh[1024];
    __shared__ int carry;
    int t = threadIdx.x;
    if (t == 0) carry = 0;
    __syncthreads();
    for (int c = 0; c < BNT / 1024; c++) {
        int idx = c * 1024 + t;
        int v = g_deg[idx];
        sh[t] = v;
        __syncthreads();
        for (int off = 1; off < 1024; off <<= 1) {
            int add = (t >= off) ? sh[t - off] : 0;
            __syncthreads();
            sh[t] += add;
            __syncthreads();
        }
        int excl = sh[t] - v + carry;
        g_off[idx] = excl;
        g_cur[idx] = excl;
        __syncthreads();
        if (t == 1023) carry = carry + sh[1023];
        __syncthreads();
    }
}

__global__ void fill_kernel() {
    int e = blockIdx.x * blockDim.x + threadIdx.x;
    if (e >= EDG) return;
    int i = e >> 4;
    int v = g_nbr[e];
    int pos = atomicAdd(&g_cur[v], 1);
    g_rev[pos] = i;
}

// ---------------- GEMM: Y[M x 2P] = A[M x Kd] @ [w_rel | w_root] (fp32) ----
__global__ void gemm_cat_kernel(const float* __restrict__ A,
                                const float* __restrict__ wr,
                                const float* __restrict__ wo,
                                float* __restrict__ Y,
                                int M, int Kd, int P) {
    __shared__ __align__(16) float As[8][128];
    __shared__ __align__(16) float Bs[8][128];
    int NN = 2 * P;
    int bm = blockIdx.y * 128;
    int bn = blockIdx.x * 128;
    int tid = threadIdx.x;
    int tx = tid & 15, ty = tid >> 4;

    float acc[8][8];
#pragma unroll
    for (int a = 0; a < 8; a++)
#pragma unroll
        for (int c = 0; c < 8; c++) acc[a][c] = 0.f;

    int a_m = tid >> 1;
    int a_k = (tid & 1) * 4;
    int b_k = tid >> 5;
    int b_n = (tid & 31) * 4;

    bool vec_a = ((Kd & 7) == 0);

    for (int k0 = 0; k0 < Kd; k0 += 8) {
        if (vec_a) {
            float4 v = *(const float4*)&A[(size_t)(bm + a_m) * Kd + k0 + a_k];
            As[a_k+0][a_m] = v.x; As[a_k+1][a_m] = v.y;
            As[a_k+2][a_m] = v.z; As[a_k+3][a_m] = v.w;
        } else {
#pragma unroll
            for (int q = 0; q < 4; q++) {
                int kk = k0 + a_k + q;
                As[a_k+q][a_m] = (kk < Kd) ? A[(size_t)(bm + a_m) * Kd + kk] : 0.f;
            }
        }
        {
            int kk = k0 + b_k;
            float4 v = make_float4(0.f, 0.f, 0.f, 0.f);
            if (kk < Kd) {
                int n = bn + b_n;
                const float* src = (n < P) ? &wr[(size_t)kk * P + n]
                                           : &wo[(size_t)kk * P + (n - P)];
                v = *(const float4*)src;
            }
            *(float4*)&Bs[b_k][b_n] = v;
        }
        __syncthreads();
#pragma unroll
        for (int kk = 0; kk < 8; kk++) {
            float af[8], bf[8];
            *(float4*)&af[0] = *(const float4*)&As[kk][ty * 8];
            *(float4*)&af[4] = *(const float4*)&As[kk][ty * 8 + 4];
            *(float4*)&bf[0] = *(const float4*)&Bs[kk][tx * 8];
            *(float4*)&bf[4] = *(const float4*)&Bs[kk][tx * 8 + 4];
#pragma unroll
            for (int ii = 0; ii < 8; ii++)
#pragma unroll
                for (int jj = 0; jj < 8; jj++)
                    acc[ii][jj] = fmaf(af[ii], bf[jj], acc[ii][jj]);
        }
        __syncthreads();
    }
#pragma unroll
    for (int ii = 0; ii < 8; ii++) {
        size_t row = (size_t)(bm + ty * 8 + ii) * NN + bn + tx * 8;
        *(float4*)&Y[row]     = make_float4(acc[ii][0], acc[ii][1], acc[ii][2], acc[ii][3]);
        *(float4*)&Y[row + 4] = make_float4(acc[ii][4], acc[ii][5], acc[ii][6], acc[ii][7]);
    }
}

// ---------------- combine v2: warp per node, float4 lanes -------------------
__global__ void combine_kernel(const float* __restrict__ Y,
                               const float* __restrict__ bias,
                               float* __restrict__ Hout,
                               int P, int do_relu) {
    int warp = threadIdx.x >> 5, lane = threadIdx.x & 31;
    int v = blockIdx.x * 4 + warp;
    int c4 = lane * 4;
    if (c4 >= P) return;
    int NN = 2 * P;
    int s = g_off[v];
    int e = s + g_deg[v];
    float4 acc = make_float4(0.f, 0.f, 0.f, 0.f);
    for (int q = s; q < e; q++) {
        int u = __ldg(&g_rev[q]);
        float4 t = *(const float4*)&Y[(size_t)u * NN + c4];
        acc.x += t.x; acc.y += t.y; acc.z += t.z; acc.w += t.w;
    }
    float4 r = *(const float4*)&Y[(size_t)v * NN + P + c4];
    float4 bv = *(const float4*)&bias[c4];
    float4 o;
    o.x = acc.x + r.x + bv.x;
    o.y = acc.y + r.y + bv.y;
    o.z = acc.z + r.z + bv.z;
    o.w = acc.w + r.w + bv.w;
    if (do_relu) {
        o.x = fmaxf(o.x, 0.f); o.y = fmaxf(o.y, 0.f);
        o.z = fmaxf(o.z, 0.f); o.w = fmaxf(o.w, 0.f);
    }
    *(float4*)&Hout[(size_t)v * P + c4] = o;
}

// ---------------- final syrk via tf32 tensor cores --------------------------
// out[b,i,j] = dot(H[b,i,:], H[b,j,:]), K=64. Block tile 128x128, 8 warps
// (4x2), warp tile 32x64 via mma.sync.m16n8k8.tf32.
#define SYRK_LD  68   // padded row stride: fragment banks = 4g + t, all distinct
#define SYRK_SMEM (2 * 128 * SYRK_LD * 4)

__device__ __forceinline__ uint32_t f2tf(float f) {
    uint32_t u;
    asm("cvt.rna.tf32.f32 %0, %1;" : "=r"(u) : "f"(f));
    return u;
}

__global__ void __launch_bounds__(256, 2) final_syrk_kernel(
        const float* __restrict__ H, float* __restrict__ out) {
    extern __shared__ float smem[];
    float* As = smem;                  // [128][SYRK_LD]
    float* Bs = smem + 128 * SYRK_LD;  // [128][SYRK_LD]
    int b  = blockIdx.z;
    int i0 = blockIdx.y * 128;
    int j0 = blockIdx.x * 128;
    const float* Hb = H + (size_t)b * Nn * 64;
    int tid = threadIdx.x;

    // load both 128x64 panels, rounding to tf32 once
#pragma unroll
    for (int q = 0; q < 8; q++) {
        int f = q * 256 + tid;          // 0..2047 float4 slots
        int r = f >> 4;
        int c = (f & 15) * 4;
        float4 va = *(const float4*)&Hb[(size_t)(i0 + r) * 64 + c];
        float4 vb = *(const float4*)&Hb[(size_t)(j0 + r) * 64 + c];
        float4 ta, tb;
        ta.x = __uint_as_float(f2tf(va.x)); ta.y = __uint_as_float(f2tf(va.y));
        ta.z = __uint_as_float(f2tf(va.z)); ta.w = __uint_as_float(f2tf(va.w));
        tb.x = __uint_as_float(f2tf(vb.x)); tb.y = __uint_as_float(f2tf(vb.y));
        tb.z = __uint_as_float(f2tf(vb.z)); tb.w = __uint_as_float(f2tf(vb.w));
        *(float4*)&As[r * SYRK_LD + c] = ta;
        *(float4*)&Bs[r * SYRK_LD + c] = tb;
    }
    __syncthreads();

    int warp = tid >> 5, lane = tid & 31;
    int wm = warp & 3;        // 0..3 -> 32-row strip
    int wn = warp >> 2;       // 0..1 -> 64-col strip
    int g  = lane >> 2;       // 0..7
    int t  = lane & 3;        // 0..3

    float acc[2][8][4];
#pragma unroll
    for (int mt = 0; mt < 2; mt++)
#pragma unroll
        for (int nt = 0; nt < 8; nt++)
#pragma unroll
            for (int e = 0; e < 4; e++) acc[mt][nt][e] = 0.f;

#pragma unroll
    for (int ks = 0; ks < 8; ks++) {
        int k0 = ks * 8;
        uint32_t a[2][4], bf[8][2];
#pragma unroll
        for (int mt = 0; mt < 2; mt++) {
            int row = wm * 32 + mt * 16;
            a[mt][0] = __float_as_uint(As[(row + g    ) * SYRK_LD + k0 + t    ]);
            a[mt][1] = __float_as_uint(As[(row + g + 8) * SYRK_LD + k0 + t    ]);
            a[mt][2] = __float_as_uint(As[(row + g    ) * SYRK_LD + k0 + t + 4]);
            a[mt][3] = __float_as_uint(As[(row + g + 8) * SYRK_LD + k0 + t + 4]);
        }
#pragma unroll
        for (int nt = 0; nt < 8; nt++) {
            int col = wn * 64 + nt * 8;
            bf[nt][0] = __float_as_uint(Bs[(col + g) * SYRK_LD + k0 + t    ]);
            bf[nt][1] = __float_as_uint(Bs[(col + g) * SYRK_LD + k0 + t + 4]);
        }
#pragma unroll
        for (int mt = 0; mt < 2; mt++)
#pragma unroll
            for (int nt = 0; nt < 8; nt++) {
                asm volatile(
                    "mma.sync.aligned.m16n8k8.row.col.f32.tf32.tf32.f32 "
                    "{%0,%1,%2,%3}, {%4,%5,%6,%7}, {%8,%9}, {%0,%1,%2,%3};"
                    : "+f"(acc[mt][nt][0]), "+f"(acc[mt][nt][1]),
                      "+f"(acc[mt][nt][2]), "+f"(acc[mt][nt][3])
                    : "r"(a[mt][0]), "r"(a[mt][1]), "r"(a[mt][2]), "r"(a[mt][3]),
                      "r"(bf[nt][0]), "r"(bf[nt][1]));
            }
    }

    float* ob = out + (size_t)b * Nn * Nn;
#pragma unroll
    for (int mt = 0; mt < 2; mt++)
#pragma unroll
        for (int nt = 0; nt < 8; nt++) {
            int row = i0 + wm * 32 + mt * 16 + g;
            int col = j0 + wn * 64 + nt * 8 + 2 * t;
            float2 lo = make_float2(acc[mt][nt][0], acc[mt][nt][1]);
            float2 hi = make_float2(acc[mt][nt][2], acc[mt][nt][3]);
            *(float2*)&ob[(size_t)row * Nn + col]       = lo;
            *(float2*)&ob[(size_t)(row + 8) * Nn + col] = hi;
        }
}

// ---------------- launch ----------------------------------------------------
extern "C" void kernel_launch(void* const* d_in, const int* in_sizes, int n_in,
                              void* d_out, int out_size) {
    const float* x   = (const float*)d_in[0];
    const float* wr0 = (const float*)d_in[1];
    const float* wo0 = (const float*)d_in[2];
    const float* bb0 = (const float*)d_in[3];
    const float* wr1 = (const float*)d_in[4];
    const float* wo1 = (const float*)d_in[5];
    const float* bb1 = (const float*)d_in[6];
    const float* wr2 = (const float*)d_in[7];
    const float* wo2 = (const float*)d_in[8];
    const float* bb2 = (const float*)d_in[9];
    const float* wr3 = (const float*)d_in[10];
    const float* wo3 = (const float*)d_in[11];
    const float* bb3 = (const float*)d_in[12];
    float* out = (float*)d_out;

    float *hA, *hB, *Y;
    cudaGetSymbolAddress((void**)&hA, g_h);
    cudaGetSymbolAddress((void**)&hB, g_hb);
    cudaGetSymbolAddress((void**)&Y,  g_y);

    cudaFuncSetAttribute(final_syrk_kernel,
                         cudaFuncAttributeMaxDynamicSharedMemorySize, SYRK_SMEM);

    // graph construction
    clear_deg_kernel<<<(BNT + 255) / 256, 256>>>();
    knn_kernel<<<BNT / 128, 128>>>(x);
    scan_kernel<<<1, 1024>>>();
    fill_kernel<<<(EDG + 255) / 256, 256>>>();

    // layer 0: x(K=10) -> 128
    gemm_cat_kernel<<<dim3(2, BNT / 128), 256>>>(x, wr0, wo0, Y, BNT, 10, 128);
    combine_kernel<<<BNT / 4, 128>>>(Y, bb0, hA, 128, 1);
    // layer 1: 128 -> 128
    gemm_cat_kernel<<<dim3(2, BNT / 128), 256>>>(hA, wr1, wo1, Y, BNT, 128, 128);
    combine_kernel<<<BNT / 4, 128>>>(Y, bb1, hB, 128, 1);
    // layer 2: 128 -> 128
    gemm_cat_kernel<<<dim3(2, BNT / 128), 256>>>(hB, wr2, wo2, Y, BNT, 128, 128);
    combine_kernel<<<BNT / 4, 128>>>(Y, bb2, hA, 128, 1);
    // layer 3: 128 -> 64 (no relu)
    gemm_cat_kernel<<<dim3(1, BNT / 128), 256>>>(hA, wr3, wo3, Y, BNT, 128, 64);
    combine_kernel<<<BNT / 4, 128>>>(Y, bb3, hB, 64, 0);

    // final bilinear via tf32 tensor cores
    final_syrk_kernel<<<dim3(Nn / 128, Nn / 128, Bb), 256, SYRK_SMEM>>>(hB, out);
}

// round 9
// speedup vs baseline: 1.8010x; 1.1487x over previous
#include <cuda_runtime.h>
#include <math_constants.h>
#include <cstdint>

#define Bb   16
#define Nn   2048
#define Cc   10
#define KK   16
#define BNT  (Bb*Nn)        // 32768 nodes
#define EDG  (BNT*KK)       // 524288 edges

// ---------------- scratch (device globals: no allocation allowed) ----------
__device__ int   g_nbr[EDG];
__device__ int   g_deg[BNT];
__device__ int   g_off[BNT];
__device__ int   g_cur[BNT];
__device__ int   g_rev[EDG];
__device__ float g_h [BNT*128];     // Acat0 = [x | aggx], row stride 20
__device__ float g_hb[BNT*128];     // final H (stride 64)
__device__ float g_a [BNT*256];     // Acat ping
__device__ float g_b [BNT*256];     // Acat pong

__global__ void clear_deg_kernel() {
    int i = blockIdx.x * blockDim.x + threadIdx.x;
    if (i < BNT) g_deg[i] = 0;
}

// ---------------- kNN: norm trick + unsorted k-best (replace-max) ----------
__global__ void knn_kernel(const float* __restrict__ x) {
    __shared__ float sn[Nn];
    __shared__ float sd[KK][128];
    __shared__ int   si[KK][128];
    int t    = threadIdx.x;
    int node = blockIdx.x * 128 + t;
    int b    = node >> 11;
    int i    = node & 2047;
    const float*  xb  = x + (size_t)b * Nn * Cc;
    const float4* xb4 = (const float4*)xb;

    for (int j = t; j < Nn; j += 128) {
        float s = 0.f;
#pragma unroll
        for (int c = 0; c < Cc; c++) { float v = xb[j * Cc + c]; s = fmaf(v, v, s); }
        sn[j] = s;
    }
    float xi[Cc];
#pragma unroll
    for (int c = 0; c < Cc; c++) xi[c] = xb[i * Cc + c];
#pragma unroll
    for (int r = 0; r < KK; r++) { sd[r][t] = CUDART_INF_F; si[r][t] = 0; }
    __syncthreads();
    float x2i = sn[i];

    float cut = CUDART_INF_F;
    int   cutpos = 0;

    for (int j0 = 0; j0 < Nn; j0 += 4) {
        float v[40];
#pragma unroll
        for (int q = 0; q < 10; q++) {
            float4 t4 = xb4[(j0 * 10) / 4 + q];
            v[q*4+0] = t4.x; v[q*4+1] = t4.y; v[q*4+2] = t4.z; v[q*4+3] = t4.w;
        }
#pragma unroll
        for (int jj = 0; jj < 4; jj++) {
            int j = j0 + jj;
            float dot = 0.f;
#pragma unroll
            for (int c = 0; c < Cc; c++) dot = fmaf(xi[c], v[jj * 10 + c], dot);
            float d2 = fmaf(-2.f, dot, x2i + sn[j]);
            if (j != i && d2 < cut) {
                sd[cutpos][t] = d2; si[cutpos][t] = j;
                float m = sd[0][t]; int mp = 0;
#pragma unroll
                for (int r = 1; r < KK; r++) {
                    float dr = sd[r][t];
                    if (dr > m) { m = dr; mp = r; }
                }
                cut = m; cutpos = mp;
            }
        }
    }
    int base = node * KK;
#pragma unroll
    for (int r = 0; r < KK; r++) {
        int nb = (b << 11) + si[r][t];
        g_nbr[base + r] = nb;
        atomicAdd(&g_deg[nb], 1);
    }
}

// ---------------- exclusive scan (shuffle-based, single block) --------------
__global__ void scan_kernel() {
    __shared__ int wsum[32];
    __shared__ int carry;
    int t = threadIdx.x, lane = t & 31, w = t >> 5;
    if (t == 0) carry = 0;
    __syncthreads();
    for (int c = 0; c < BNT / 1024; c++) {
        int idx = c * 1024 + t;
        int v = g_deg[idx];
        int inc = v;
#pragma unroll
        for (int o = 1; o < 32; o <<= 1) {
            int n = __shfl_up_sync(0xffffffffu, inc, o);
            if (lane >= o) inc += n;
        }
        if (lane == 31) wsum[w] = inc;
        __syncthreads();
        if (w == 0) {
            int s = wsum[lane];
#pragma unroll
            for (int o = 1; o < 32; o <<= 1) {
                int n = __shfl_up_sync(0xffffffffu, s, o);
                if (lane >= o) s += n;
            }
            wsum[lane] = s;
        }
        __syncthreads();
        int base = carry + ((w > 0) ? wsum[w - 1] : 0);
        int excl = base + inc - v;
        g_off[idx] = excl;
        g_cur[idx] = excl;
        __syncthreads();
        if (t == 1023) carry = carry + wsum[31];
        __syncthreads();
    }
}

__global__ void fill_kernel() {
    int e = blockIdx.x * blockDim.x + threadIdx.x;
    if (e >= EDG) return;
    int i = e >> 4;
    int v = g_nbr[e];
    int pos = atomicAdd(&g_cur[v], 1);
    g_rev[pos] = i;
}

// ---------------- layer-0 concat: Acat0[v] = [x_v (10) | sum x_u (10)] -----
__global__ void aggx_kernel(const float* __restrict__ x, float* __restrict__ acat) {
    int warp = threadIdx.x >> 5, lane = threadIdx.x & 31;
    int v = blockIdx.x * 8 + warp;
    float xv = 0.f, acc = 0.f;
    if (lane < 10) xv = x[(size_t)v * 10 + lane];
    int s = g_off[v];
    int e = s + g_deg[v];
    for (int q = s; q < e; q++) {
        int u = __ldg(&g_rev[q]);
        if (lane < 10) acc += x[(size_t)u * 10 + lane];
    }
    if (lane < 10) {
        acat[(size_t)v * 20 + lane]      = xv;
        acat[(size_t)v * 20 + 10 + lane] = acc;
    }
}

// ---------------- aggregate (128-wide): buf[v][128..255] = sum buf[u][0..127]
__global__ void agg128_kernel(float* __restrict__ buf) {
    int warp = threadIdx.x >> 5, lane = threadIdx.x & 31;
    int v = blockIdx.x * 8 + warp;
    int c4 = lane * 4;
    int s = g_off[v];
    int e = s + g_deg[v];
    float4 acc = make_float4(0.f, 0.f, 0.f, 0.f);
    for (int q = s; q < e; q++) {
        int u = __ldg(&g_rev[q]);
        float4 t = *(const float4*)&buf[(size_t)u * 256 + c4];
        acc.x += t.x; acc.y += t.y; acc.z += t.z; acc.w += t.w;
    }
    *(float4*)&buf[(size_t)v * 256 + 128 + c4] = acc;
}

// ---------------- tf32 layer GEMM: Out = relu(Acat @ [wo;wr] + b) ----------
// M-tile 128, N<=128, K-tile 16, 256 threads (8 warps, warp tile 32x64).
// k < Khalf -> wo rows, k >= Khalf -> wr rows (Acat = [root | agg]).
#define GLDA 17

__device__ __forceinline__ float f2tf_f(float f) {
    uint32_t u;
    asm("cvt.rna.tf32.f32 %0, %1;" : "=r"(u) : "f"(f));
    return __uint_as_float(u);
}

__global__ void __launch_bounds__(256, 2) gemm_tf32_kernel(
        const float* __restrict__ A, int lda, int K, int Khalf,
        const float* __restrict__ wo, const float* __restrict__ wr, int P,
        const float* __restrict__ bias, float* __restrict__ Out, int ldo,
        int do_relu) {
    __shared__ float As[128 * GLDA];
    __shared__ float Ws[128 * GLDA];
    int bm  = blockIdx.x * 128;
    int tid = threadIdx.x;
    int r2  = tid >> 1;              // 0..127: A row / W col
    int kh  = (tid & 1) * 8;         // 0 or 8
    int warp = tid >> 5, lane = tid & 31;
    int wm = warp & 3, wn = warp >> 2;
    int g  = lane >> 2, t4 = lane & 3;

    float acc[2][8][4];
#pragma unroll
    for (int mt = 0; mt < 2; mt++)
#pragma unroll
        for (int nt = 0; nt < 8; nt++)
#pragma unroll
            for (int e = 0; e < 4; e++) acc[mt][nt][e] = 0.f;

    for (int k0 = 0; k0 < K; k0 += 16) {
        // stage A[128][16] -> As (tf32)
        const float* Ap = &A[(size_t)(bm + r2) * lda + k0 + kh];
        if (k0 + kh + 8 <= K) {
            float4 v0 = *(const float4*)Ap;
            float4 v1 = *(const float4*)(Ap + 4);
            As[r2 * GLDA + kh + 0] = f2tf_f(v0.x);
            As[r2 * GLDA + kh + 1] = f2tf_f(v0.y);
            As[r2 * GLDA + kh + 2] = f2tf_f(v0.z);
            As[r2 * GLDA + kh + 3] = f2tf_f(v0.w);
            As[r2 * GLDA + kh + 4] = f2tf_f(v1.x);
            As[r2 * GLDA + kh + 5] = f2tf_f(v1.y);
            As[r2 * GLDA + kh + 6] = f2tf_f(v1.z);
            As[r2 * GLDA + kh + 7] = f2tf_f(v1.w);
        } else {
#pragma unroll
            for (int q = 0; q < 8; q++) {
                int kk = k0 + kh + q;
                As[r2 * GLDA + kh + q] = (kk < K) ? f2tf_f(Ap[q]) : 0.f;
            }
        }
        // stage W^T[128 n][16 k] -> Ws (tf32)
#pragma unroll
        for (int q = 0; q < 8; q++) {
            int kk = k0 + kh + q;
            float v = 0.f;
            if (kk < K && r2 < P)
                v = (kk < Khalf) ? wo[(size_t)kk * P + r2]
                                 : wr[(size_t)(kk - Khalf) * P + r2];
            Ws[r2 * GLDA + kh + q] = f2tf_f(v);
        }
        __syncthreads();
#pragma unroll
        for (int ks = 0; ks < 16; ks += 8) {
            uint32_t a[2][4], bfr[8][2];
#pragma unroll
            for (int mt = 0; mt < 2; mt++) {
                int row = wm * 32 + mt * 16;
                a[mt][0] = __float_as_uint(As[(row + g    ) * GLDA + ks + t4    ]);
                a[mt][1] = __float_as_uint(As[(row + g + 8) * GLDA + ks + t4    ]);
                a[mt][2] = __float_as_uint(As[(row + g    ) * GLDA + ks + t4 + 4]);
                a[mt][3] = __float_as_uint(As[(row + g + 8) * GLDA + ks + t4 + 4]);
            }
#pragma unroll
            for (int nt = 0; nt < 8; nt++) {
                int col = wn * 64 + nt * 8;
                bfr[nt][0] = __float_as_uint(Ws[(col + g) * GLDA + ks + t4    ]);
                bfr[nt][1] = __float_as_uint(Ws[(col + g) * GLDA + ks + t4 + 4]);
            }
#pragma unroll
            for (int mt = 0; mt < 2; mt++)
#pragma unroll
                for (int nt = 0; nt < 8; nt++) {
                    asm volatile(
                        "mma.sync.aligned.m16n8k8.row.col.f32.tf32.tf32.f32 "
                        "{%0,%1,%2,%3}, {%4,%5,%6,%7}, {%8,%9}, {%0,%1,%2,%3};"
                        : "+f"(acc[mt][nt][0]), "+f"(acc[mt][nt][1]),
                          "+f"(acc[mt][nt][2]), "+f"(acc[mt][nt][3])
                        : "r"(a[mt][0]), "r"(a[mt][1]), "r"(a[mt][2]), "r"(a[mt][3]),
                          "r"(bfr[nt][0]), "r"(bfr[nt][1]));
                }
        }
        __syncthreads();
    }

    // epilogue: bias + optional relu
#pragma unroll
    for (int nt = 0; nt < 8; nt++) {
        int col = wn * 64 + nt * 8 + 2 * t4;
        if (col >= P) continue;
        float b0 = bias[col], b1 = bias[col + 1];
#pragma unroll
        for (int mt = 0; mt < 2; mt++) {
            int row = bm + wm * 32 + mt * 16 + g;
            float o0 = acc[mt][nt][0] + b0;
            float o1 = acc[mt][nt][1] + b1;
            float o2 = acc[mt][nt][2] + b0;
            float o3 = acc[mt][nt][3] + b1;
            if (do_relu) {
                o0 = fmaxf(o0, 0.f); o1 = fmaxf(o1, 0.f);
                o2 = fmaxf(o2, 0.f); o3 = fmaxf(o3, 0.f);
            }
            *(float2*)&Out[(size_t)row * ldo + col]       = make_float2(o0, o1);
            *(float2*)&Out[(size_t)(row + 8) * ldo + col] = make_float2(o2, o3);
        }
    }
}

// ---------------- final syrk via tf32 tensor cores --------------------------
#define SYRK_LD  68
#define SYRK_SMEM (2 * 128 * SYRK_LD * 4)

__device__ __forceinline__ uint32_t f2tf(float f) {
    uint32_t u;
    asm("cvt.rna.tf32.f32 %0, %1;" : "=r"(u) : "f"(f));
    return u;
}

__global__ void __launch_bounds__(256, 2) final_syrk_kernel(
        const float* __restrict__ H, float* __restrict__ out) {
    extern __shared__ float smem[];
    float* As = smem;
    float* Bs = smem + 128 * SYRK_LD;
    int b  = blockIdx.z;
    int i0 = blockIdx.y * 128;
    int j0 = blockIdx.x * 128;
    const float* Hb = H + (size_t)b * Nn * 64;
    int tid = threadIdx.x;

#pragma unroll
    for (int q = 0; q < 8; q++) {
        int f = q * 256 + tid;
        int r = f >> 4;
        int c = (f & 15) * 4;
        float4 va = *(const float4*)&Hb[(size_t)(i0 + r) * 64 + c];
        float4 vb = *(const float4*)&Hb[(size_t)(j0 + r) * 64 + c];
        float4 ta, tb;
        ta.x = __uint_as_float(f2tf(va.x)); ta.y = __uint_as_float(f2tf(va.y));
        ta.z = __uint_as_float(f2tf(va.z)); ta.w = __uint_as_float(f2tf(va.w));
        tb.x = __uint_as_float(f2tf(vb.x)); tb.y = __uint_as_float(f2tf(vb.y));
        tb.z = __uint_as_float(f2tf(vb.z)); tb.w = __uint_as_float(f2tf(vb.w));
        *(float4*)&As[r * SYRK_LD + c] = ta;
        *(float4*)&Bs[r * SYRK_LD + c] = tb;
    }
    __syncthreads();

    int warp = tid >> 5, lane = tid & 31;
    int wm = warp & 3;
    int wn = warp >> 2;
    int g  = lane >> 2;
    int t  = lane & 3;

    float acc[2][8][4];
#pragma unroll
    for (int mt = 0; mt < 2; mt++)
#pragma unroll
        for (int nt = 0; nt < 8; nt++)
#pragma unroll
            for (int e = 0; e < 4; e++) acc[mt][nt][e] = 0.f;

#pragma unroll
    for (int ks = 0; ks < 8; ks++) {
        int k0 = ks * 8;
        uint32_t a[2][4], bf[8][2];
#pragma unroll
        for (int mt = 0; mt < 2; mt++) {
            int row = wm * 32 + mt * 16;
            a[mt][0] = __float_as_uint(As[(row + g    ) * SYRK_LD + k0 + t    ]);
            a[mt][1] = __float_as_uint(As[(row + g + 8) * SYRK_LD + k0 + t    ]);
            a[mt][2] = __float_as_uint(As[(row + g    ) * SYRK_LD + k0 + t + 4]);
            a[mt][3] = __float_as_uint(As[(row + g + 8) * SYRK_LD + k0 + t + 4]);
        }
#pragma unroll
        for (int nt = 0; nt < 8; nt++) {
            int col = wn * 64 + nt * 8;
            bf[nt][0] = __float_as_uint(Bs[(col + g) * SYRK_LD + k0 + t    ]);
            bf[nt][1] = __float_as_uint(Bs[(col + g) * SYRK_LD + k0 + t + 4]);
        }
#pragma unroll
        for (int mt = 0; mt < 2; mt++)
#pragma unroll
            for (int nt = 0; nt < 8; nt++) {
                asm volatile(
                    "mma.sync.aligned.m16n8k8.row.col.f32.tf32.tf32.f32 "
                    "{%0,%1,%2,%3}, {%4,%5,%6,%7}, {%8,%9}, {%0,%1,%2,%3};"
                    : "+f"(acc[mt][nt][0]), "+f"(acc[mt][nt][1]),
                      "+f"(acc[mt][nt][2]), "+f"(acc[mt][nt][3])
                    : "r"(a[mt][0]), "r"(a[mt][1]), "r"(a[mt][2]), "r"(a[mt][3]),
                      "r"(bf[nt][0]), "r"(bf[nt][1]));
            }
    }

    float* ob = out + (size_t)b * Nn * Nn;
#pragma unroll
    for (int mt = 0; mt < 2; mt++)
#pragma unroll
        for (int nt = 0; nt < 8; nt++) {
            int row = i0 + wm * 32 + mt * 16 + g;
            int col = j0 + wn * 64 + nt * 8 + 2 * t;
            float2 lo = make_float2(acc[mt][nt][0], acc[mt][nt][1]);
            float2 hi = make_float2(acc[mt][nt][2], acc[mt][nt][3]);
            *(float2*)&ob[(size_t)row * Nn + col]       = lo;
            *(float2*)&ob[(size_t)(row + 8) * Nn + col] = hi;
        }
}

// ---------------- launch ----------------------------------------------------
extern "C" void kernel_launch(void* const* d_in, const int* in_sizes, int n_in,
                              void* d_out, int out_size) {
    const float* x   = (const float*)d_in[0];
    const float* wr0 = (const float*)d_in[1];
    const float* wo0 = (const float*)d_in[2];
    const float* bb0 = (const float*)d_in[3];
    const float* wr1 = (const float*)d_in[4];
    const float* wo1 = (const float*)d_in[5];
    const float* bb1 = (const float*)d_in[6];
    const float* wr2 = (const float*)d_in[7];
    const float* wo2 = (const float*)d_in[8];
    const float* bb2 = (const float*)d_in[9];
    const float* wr3 = (const float*)d_in[10];
    const float* wo3 = (const float*)d_in[11];
    const float* bb3 = (const float*)d_in[12];
    float* out = (float*)d_out;

    float *acat0, *H, *A, *B;
    cudaGetSymbolAddress((void**)&acat0, g_h);
    cudaGetSymbolAddress((void**)&H,     g_hb);
    cudaGetSymbolAddress((void**)&A,     g_a);
    cudaGetSymbolAddress((void**)&B,     g_b);

    cudaFuncSetAttribute(final_syrk_kernel,
                         cudaFuncAttributeMaxDynamicSharedMemorySize, SYRK_SMEM);

    // graph construction
    clear_deg_kernel<<<(BNT + 255) / 256, 256>>>();
    knn_kernel<<<BNT / 128, 128>>>(x);
    scan_kernel<<<1, 1024>>>();
    fill_kernel<<<(EDG + 255) / 256, 256>>>();

    // layer 0: Acat0 = [x | agg(x)] (K=20) -> h1 (128) into A left half
    aggx_kernel<<<BNT / 8, 256>>>(x, acat0);
    gemm_tf32_kernel<<<BNT / 128, 256>>>(acat0, 20, 20, 10, wo0, wr0, 128,
                                         bb0, A, 256, 1);
    // layer 1: A=[h1|agg] -> h2 into B left half
    agg128_kernel<<<BNT / 8, 256>>>(A);
    gemm_tf32_kernel<<<BNT / 128, 256>>>(A, 256, 256, 128, wo1, wr1, 128,
                                         bb1, B, 256, 1);
    // layer 2: B -> h3 into A left half
    agg128_kernel<<<BNT / 8, 256>>>(B);
    gemm_tf32_kernel<<<BNT / 128, 256>>>(B, 256, 256, 128, wo2, wr2, 128,
                                         bb2, A, 256, 1);
    // layer 3: A -> H (64-wide, no relu)
    agg128_kernel<<<BNT / 8, 256>>>(A);
    gemm_tf32_kernel<<<BNT / 128, 256>>>(A, 256, 256, 128, wo3, wr3, 64,
                                         bb3, H, 64, 0);

    // final bilinear via tf32 tensor cores
    final_syrk_kernel<<<dim3(Nn / 128, Nn / 128, Bb), 256, SYRK_SMEM>>>(H, out);
}

// round 10
// speedup vs baseline: 1.8779x; 1.0427x over previous
#include <cuda_runtime.h>
#include <math_constants.h>
#include <cstdint>

#define Bb   16
#define Nn   2048
#define Cc   10
#define KK   16
#define BNT  (Bb*Nn)        // 32768 nodes
#define EDG  (BNT*KK)       // 524288 edges

// ---------------- scratch (device globals: no allocation allowed) ----------
__device__ int   g_nbr[EDG];
__device__ int   g_deg[BNT];
__device__ int   g_off[BNT];
__device__ int   g_cur[BNT];
__device__ int   g_rev[EDG];
__device__ float g_h [BNT*128];     // Acat0 (stride 20)
__device__ float g_hb[BNT*128];     // final H (stride 64)
__device__ float g_a [BNT*256];     // h1 / h3 (stride 128)
__device__ float g_b [BNT*256];     // h2 (stride 128)

__global__ void clear_deg_kernel() {
    int i = blockIdx.x * blockDim.x + threadIdx.x;
    if (i < BNT) g_deg[i] = 0;
}

// ---------------- kNN: norm trick + unsorted k-best (replace-max) ----------
__global__ void knn_kernel(const float* __restrict__ x) {
    __shared__ float sn[Nn];
    __shared__ float sd[KK][128];
    __shared__ int   si[KK][128];
    int t    = threadIdx.x;
    int node = blockIdx.x * 128 + t;
    int b    = node >> 11;
    int i    = node & 2047;
    const float*  xb  = x + (size_t)b * Nn * Cc;
    const float4* xb4 = (const float4*)xb;

    for (int j = t; j < Nn; j += 128) {
        float s = 0.f;
#pragma unroll
        for (int c = 0; c < Cc; c++) { float v = xb[j * Cc + c]; s = fmaf(v, v, s); }
        sn[j] = s;
    }
    float xi[Cc];
#pragma unroll
    for (int c = 0; c < Cc; c++) xi[c] = xb[i * Cc + c];
#pragma unroll
    for (int r = 0; r < KK; r++) { sd[r][t] = CUDART_INF_F; si[r][t] = 0; }
    __syncthreads();
    float x2i = sn[i];

    float cut = CUDART_INF_F;
    int   cutpos = 0;

    for (int j0 = 0; j0 < Nn; j0 += 4) {
        float v[40];
#pragma unroll
        for (int q = 0; q < 10; q++) {
            float4 t4 = xb4[(j0 * 10) / 4 + q];
            v[q*4+0] = t4.x; v[q*4+1] = t4.y; v[q*4+2] = t4.z; v[q*4+3] = t4.w;
        }
#pragma unroll
        for (int jj = 0; jj < 4; jj++) {
            int j = j0 + jj;
            float dot = 0.f;
#pragma unroll
            for (int c = 0; c < Cc; c++) dot = fmaf(xi[c], v[jj * 10 + c], dot);
            float d2 = fmaf(-2.f, dot, x2i + sn[j]);
            if (j != i && d2 < cut) {
                sd[cutpos][t] = d2; si[cutpos][t] = j;
                float m = sd[0][t]; int mp = 0;
#pragma unroll
                for (int r = 1; r < KK; r++) {
                    float dr = sd[r][t];
                    if (dr > m) { m = dr; mp = r; }
                }
                cut = m; cutpos = mp;
            }
        }
    }
    int base = node * KK;
#pragma unroll
    for (int r = 0; r < KK; r++) {
        int nb = (b << 11) + si[r][t];
        g_nbr[base + r] = nb;
        atomicAdd(&g_deg[nb], 1);
    }
}

// ---------------- exclusive scan (shuffle-based, single block) --------------
__global__ void scan_kernel() {
    __shared__ int wsum[32];
    __shared__ int carry;
    int t = threadIdx.x, lane = t & 31, w = t >> 5;
    if (t == 0) carry = 0;
    __syncthreads();
    for (int c = 0; c < BNT / 1024; c++) {
        int idx = c * 1024 + t;
        int v = g_deg[idx];
        int inc = v;
#pragma unroll
        for (int o = 1; o < 32; o <<= 1) {
            int n = __shfl_up_sync(0xffffffffu, inc, o);
            if (lane >= o) inc += n;
        }
        if (lane == 31) wsum[w] = inc;
        __syncthreads();
        if (w == 0) {
            int s = wsum[lane];
#pragma unroll
            for (int o = 1; o < 32; o <<= 1) {
                int n = __shfl_up_sync(0xffffffffu, s, o);
                if (lane >= o) s += n;
            }
            wsum[lane] = s;
        }
        __syncthreads();
        int base = carry + ((w > 0) ? wsum[w - 1] : 0);
        int excl = base + inc - v;
        g_off[idx] = excl;
        g_cur[idx] = excl;
        __syncthreads();
        if (t == 1023) carry = carry + wsum[31];
        __syncthreads();
    }
}

__global__ void fill_kernel() {
    int e = blockIdx.x * blockDim.x + threadIdx.x;
    if (e >= EDG) return;
    int i = e >> 4;
    int v = g_nbr[e];
    int pos = atomicAdd(&g_cur[v], 1);
    g_rev[pos] = i;
}

// ---------------- layer-0 concat: Acat0[v] = [x_v (10) | sum x_u (10)] -----
__global__ void aggx_kernel(const float* __restrict__ x, float* __restrict__ acat) {
    int warp = threadIdx.x >> 5, lane = threadIdx.x & 31;
    int v = blockIdx.x * 8 + warp;
    float xv = 0.f, acc = 0.f;
    if (lane < 10) xv = x[(size_t)v * 10 + lane];
    int s = g_off[v];
    int e = s + g_deg[v];
    for (int q = s; q < e; q++) {
        int u = __ldg(&g_rev[q]);
        if (lane < 10) acc += x[(size_t)u * 10 + lane];
    }
    if (lane < 10) {
        acat[(size_t)v * 20 + lane]      = xv;
        acat[(size_t)v * 20 + 10 + lane] = acc;
    }
}

// ---------------- tf32 helpers ----------------------------------------------
__device__ __forceinline__ float f2tf_f(float f) {
    uint32_t u;
    asm("cvt.rna.tf32.f32 %0, %1;" : "=r"(u) : "f"(f));
    return __uint_as_float(u);
}
__device__ __forceinline__ uint32_t f2tf(float f) {
    uint32_t u;
    asm("cvt.rna.tf32.f32 %0, %1;" : "=r"(u) : "f"(f));
    return u;
}

#define GLDA 17

// ---------------- generic tf32 GEMM (layer 0): Out = relu(A@[wo;wr]+b) ------
__global__ void __launch_bounds__(256, 2) gemm_tf32_kernel(
        const float* __restrict__ A, int lda, int K, int Khalf,
        const float* __restrict__ wo, const float* __restrict__ wr, int P,
        const float* __restrict__ bias, float* __restrict__ Out, int ldo,
        int do_relu) {
    __shared__ float As[128 * GLDA];
    __shared__ float Ws[128 * GLDA];
    int bm  = blockIdx.x * 128;
    int tid = threadIdx.x;
    int r2  = tid >> 1;
    int kh  = (tid & 1) * 8;
    int warp = tid >> 5, lane = tid & 31;
    int wm = warp & 3, wn = warp >> 2;
    int g  = lane >> 2, t4 = lane & 3;

    float acc[2][8][4];
#pragma unroll
    for (int mt = 0; mt < 2; mt++)
#pragma unroll
        for (int nt = 0; nt < 8; nt++)
#pragma unroll
            for (int e = 0; e < 4; e++) acc[mt][nt][e] = 0.f;

    for (int k0 = 0; k0 < K; k0 += 16) {
        const float* Ap = &A[(size_t)(bm + r2) * lda + k0 + kh];
        if (k0 + kh + 8 <= K) {
            float4 v0 = *(const float4*)Ap;
            float4 v1 = *(const float4*)(Ap + 4);
            As[r2 * GLDA + kh + 0] = f2tf_f(v0.x);
            As[r2 * GLDA + kh + 1] = f2tf_f(v0.y);
            As[r2 * GLDA + kh + 2] = f2tf_f(v0.z);
            As[r2 * GLDA + kh + 3] = f2tf_f(v0.w);
            As[r2 * GLDA + kh + 4] = f2tf_f(v1.x);
            As[r2 * GLDA + kh + 5] = f2tf_f(v1.y);
            As[r2 * GLDA + kh + 6] = f2tf_f(v1.z);
            As[r2 * GLDA + kh + 7] = f2tf_f(v1.w);
        } else {
#pragma unroll
            for (int q = 0; q < 8; q++) {
                int kk = k0 + kh + q;
                As[r2 * GLDA + kh + q] = (kk < K) ? f2tf_f(Ap[q]) : 0.f;
            }
        }
#pragma unroll
        for (int q = 0; q < 8; q++) {
            int kk = k0 + kh + q;
            float v = 0.f;
            if (kk < K && r2 < P)
                v = (kk < Khalf) ? wo[(size_t)kk * P + r2]
                                 : wr[(size_t)(kk - Khalf) * P + r2];
            Ws[r2 * GLDA + kh + q] = f2tf_f(v);
        }
        __syncthreads();
#pragma unroll
        for (int ks = 0; ks < 16; ks += 8) {
            uint32_t a[2][4], bfr[8][2];
#pragma unroll
            for (int mt = 0; mt < 2; mt++) {
                int row = wm * 32 + mt * 16;
                a[mt][0] = __float_as_uint(As[(row + g    ) * GLDA + ks + t4    ]);
                a[mt][1] = __float_as_uint(As[(row + g + 8) * GLDA + ks + t4    ]);
                a[mt][2] = __float_as_uint(As[(row + g    ) * GLDA + ks + t4 + 4]);
                a[mt][3] = __float_as_uint(As[(row + g + 8) * GLDA + ks + t4 + 4]);
            }
#pragma unroll
            for (int nt = 0; nt < 8; nt++) {
                int col = wn * 64 + nt * 8;
                bfr[nt][0] = __float_as_uint(Ws[(col + g) * GLDA + ks + t4    ]);
                bfr[nt][1] = __float_as_uint(Ws[(col + g) * GLDA + ks + t4 + 4]);
            }
#pragma unroll
            for (int mt = 0; mt < 2; mt++)
#pragma unroll
                for (int nt = 0; nt < 8; nt++) {
                    asm volatile(
                        "mma.sync.aligned.m16n8k8.row.col.f32.tf32.tf32.f32 "
                        "{%0,%1,%2,%3}, {%4,%5,%6,%7}, {%8,%9}, {%0,%1,%2,%3};"
                        : "+f"(acc[mt][nt][0]), "+f"(acc[mt][nt][1]),
                          "+f"(acc[mt][nt][2]), "+f"(acc[mt][nt][3])
                        : "r"(a[mt][0]), "r"(a[mt][1]), "r"(a[mt][2]), "r"(a[mt][3]),
                          "r"(bfr[nt][0]), "r"(bfr[nt][1]));
                }
        }
        __syncthreads();
    }

#pragma unroll
    for (int nt = 0; nt < 8; nt++) {
        int col = wn * 64 + nt * 8 + 2 * t4;
        if (col >= P) continue;
        float b0 = bias[col], b1 = bias[col + 1];
#pragma unroll
        for (int mt = 0; mt < 2; mt++) {
            int row = bm + wm * 32 + mt * 16 + g;
            float o0 = acc[mt][nt][0] + b0;
            float o1 = acc[mt][nt][1] + b1;
            float o2 = acc[mt][nt][2] + b0;
            float o3 = acc[mt][nt][3] + b1;
            if (do_relu) {
                o0 = fmaxf(o0, 0.f); o1 = fmaxf(o1, 0.f);
                o2 = fmaxf(o2, 0.f); o3 = fmaxf(o3, 0.f);
            }
            *(float2*)&Out[(size_t)row * ldo + col]       = make_float2(o0, o1);
            *(float2*)&Out[(size_t)(row + 8) * ldo + col] = make_float2(o2, o3);
        }
    }
}

// ---------------- fused gather+GEMM (layers 1-3) -----------------------------
// h: [BNT][128]. Per block: gather agg[v]=sum_u h[u] into smem (tf32),
// then Out = relu([h | agg] @ [wo;wr] + b). Right K-half reads mma fragments
// directly from the agg smem (stride 132 -> banks g*4+t4, conflict-free).
#define FLDT 132
#define FUSED_SMEM ((128 * FLDT + 2 * 128 * GLDA) * 4)

__global__ void __launch_bounds__(256, 2) gemm_fused_kernel(
        const float* __restrict__ h,
        const float* __restrict__ wo, const float* __restrict__ wr, int P,
        const float* __restrict__ bias, float* __restrict__ Out, int ldo,
        int do_relu) {
    extern __shared__ float sm[];
    float* agg = sm;                       // [128][FLDT]
    float* As  = sm + 128 * FLDT;          // [128][GLDA]
    float* Ws  = As + 128 * GLDA;          // [128][GLDA]
    int bm  = blockIdx.x * 128;
    int tid = threadIdx.x;
    int warp = tid >> 5, lane = tid & 31;

    // ---- gather neighbor sums for this block's 128 nodes ----
#pragma unroll 1
    for (int s = 0; s < 16; s++) {
        int r = warp * 16 + s;
        int v = bm + r;
        int c4 = lane * 4;
        int off = g_off[v];
        int deg = g_deg[v];
        float4 acc = make_float4(0.f, 0.f, 0.f, 0.f);
        for (int q = 0; q < deg; q++) {
            int u = __ldg(&g_rev[off + q]);
            float4 t = *(const float4*)&h[(size_t)u * 128 + c4];
            acc.x += t.x; acc.y += t.y; acc.z += t.z; acc.w += t.w;
        }
        float4 ta;
        ta.x = f2tf_f(acc.x); ta.y = f2tf_f(acc.y);
        ta.z = f2tf_f(acc.z); ta.w = f2tf_f(acc.w);
        *(float4*)&agg[r * FLDT + c4] = ta;
    }
    __syncthreads();

    int r2 = tid >> 1;
    int kh = (tid & 1) * 8;
    int wm = warp & 3, wn = warp >> 2;
    int g  = lane >> 2, t4 = lane & 3;

    float acc[2][8][4];
#pragma unroll
    for (int mt = 0; mt < 2; mt++)
#pragma unroll
        for (int nt = 0; nt < 8; nt++)
#pragma unroll
            for (int e = 0; e < 4; e++) acc[mt][nt][e] = 0.f;

    // ---- left K-half: root features from global h (staged) ----
    for (int k0 = 0; k0 < 128; k0 += 16) {
        const float* Ap = &h[(size_t)(bm + r2) * 128 + k0 + kh];
        float4 v0 = *(const float4*)Ap;
        float4 v1 = *(const float4*)(Ap + 4);
        As[r2 * GLDA + kh + 0] = f2tf_f(v0.x);
        As[r2 * GLDA + kh + 1] = f2tf_f(v0.y);
        As[r2 * GLDA + kh + 2] = f2tf_f(v0.z);
        As[r2 * GLDA + kh + 3] = f2tf_f(v0.w);
        As[r2 * GLDA + kh + 4] = f2tf_f(v1.x);
        As[r2 * GLDA + kh + 5] = f2tf_f(v1.y);
        As[r2 * GLDA + kh + 6] = f2tf_f(v1.z);
        As[r2 * GLDA + kh + 7] = f2tf_f(v1.w);
#pragma unroll
        for (int q = 0; q < 8; q++) {
            int kk = k0 + kh + q;
            float v = (r2 < P) ? wo[(size_t)kk * P + r2] : 0.f;
            Ws[r2 * GLDA + kh + q] = f2tf_f(v);
        }
        __syncthreads();
#pragma unroll
        for (int ks = 0; ks < 16; ks += 8) {
            uint32_t a[2][4], bfr[8][2];
#pragma unroll
            for (int mt = 0; mt < 2; mt++) {
                int row = wm * 32 + mt * 16;
                a[mt][0] = __float_as_uint(As[(row + g    ) * GLDA + ks + t4    ]);
                a[mt][1] = __float_as_uint(As[(row + g + 8) * GLDA + ks + t4    ]);
                a[mt][2] = __float_as_uint(As[(row + g    ) * GLDA + ks + t4 + 4]);
                a[mt][3] = __float_as_uint(As[(row + g + 8) * GLDA + ks + t4 + 4]);
            }
#pragma unroll
            for (int nt = 0; nt < 8; nt++) {
                int col = wn * 64 + nt * 8;
                bfr[nt][0] = __float_as_uint(Ws[(col + g) * GLDA + ks + t4    ]);
                bfr[nt][1] = __float_as_uint(Ws[(col + g) * GLDA + ks + t4 + 4]);
            }
#pragma unroll
            for (int mt = 0; mt < 2; mt++)
#pragma unroll
                for (int nt = 0; nt < 8; nt++) {
                    asm volatile(
                        "mma.sync.aligned.m16n8k8.row.col.f32.tf32.tf32.f32 "
                        "{%0,%1,%2,%3}, {%4,%5,%6,%7}, {%8,%9}, {%0,%1,%2,%3};"
                        : "+f"(acc[mt][nt][0]), "+f"(acc[mt][nt][1]),
                          "+f"(acc[mt][nt][2]), "+f"(acc[mt][nt][3])
                        : "r"(a[mt][0]), "r"(a[mt][1]), "r"(a[mt][2]), "r"(a[mt][3]),
                          "r"(bfr[nt][0]), "r"(bfr[nt][1]));
                }
        }
        __syncthreads();
    }

    // ---- right K-half: aggregated features from smem (direct fragments) ----
    for (int k0 = 0; k0 < 128; k0 += 16) {
#pragma unroll
        for (int q = 0; q < 8; q++) {
            int kk = k0 + kh + q;
            float v = (r2 < P) ? wr[(size_t)kk * P + r2] : 0.f;
            Ws[r2 * GLDA + kh + q] = f2tf_f(v);
        }
        __syncthreads();
#pragma unroll
        for (int ks = 0; ks < 16; ks += 8) {
            int kb = k0 + ks;
            uint32_t a[2][4], bfr[8][2];
#pragma unroll
            for (int mt = 0; mt < 2; mt++) {
                int row = wm * 32 + mt * 16;
                a[mt][0] = __float_as_uint(agg[(row + g    ) * FLDT + kb + t4    ]);
                a[mt][1] = __float_as_uint(agg[(row + g + 8) * FLDT + kb + t4    ]);
                a[mt][2] = __float_as_uint(agg[(row + g    ) * FLDT + kb + t4 + 4]);
                a[mt][3] = __float_as_uint(agg[(row + g + 8) * FLDT + kb + t4 + 4]);
            }
#pragma unroll
            for (int nt = 0; nt < 8; nt++) {
                int col = wn * 64 + nt * 8;
                bfr[nt][0] = __float_as_uint(Ws[(col + g) * GLDA + ks + t4    ]);
                bfr[nt][1] = __float_as_uint(Ws[(col + g) * GLDA + ks + t4 + 4]);
            }
#pragma unroll
            for (int mt = 0; mt < 2; mt++)
#pragma unroll
                for (int nt = 0; nt < 8; nt++) {
                    asm volatile(
                        "mma.sync.aligned.m16n8k8.row.col.f32.tf32.tf32.f32 "
                        "{%0,%1,%2,%3}, {%4,%5,%6,%7}, {%8,%9}, {%0,%1,%2,%3};"
                        : "+f"(acc[mt][nt][0]), "+f"(acc[mt][nt][1]),
                          "+f"(acc[mt][nt][2]), "+f"(acc[mt][nt][3])
                        : "r"(a[mt][0]), "r"(a[mt][1]), "r"(a[mt][2]), "r"(a[mt][3]),
                          "r"(bfr[nt][0]), "r"(bfr[nt][1]));
                }
        }
        __syncthreads();
    }

    // ---- epilogue: bias + optional relu ----
#pragma unroll
    for (int nt = 0; nt < 8; nt++) {
        int col = wn * 64 + nt * 8 + 2 * t4;
        if (col >= P) continue;
        float b0 = bias[col], b1 = bias[col + 1];
#pragma unroll
        for (int mt = 0; mt < 2; mt++) {
            int row = bm + wm * 32 + mt * 16 + g;
            float o0 = acc[mt][nt][0] + b0;
            float o1 = acc[mt][nt][1] + b1;
            float o2 = acc[mt][nt][2] + b0;
            float o3 = acc[mt][nt][3] + b1;
            if (do_relu) {
                o0 = fmaxf(o0, 0.f); o1 = fmaxf(o1, 0.f);
                o2 = fmaxf(o2, 0.f); o3 = fmaxf(o3, 0.f);
            }
            *(float2*)&Out[(size_t)row * ldo + col]       = make_float2(o0, o1);
            *(float2*)&Out[(size_t)(row + 8) * ldo + col] = make_float2(o2, o3);
        }
    }
}

// ---------------- final syrk (tf32 tensor cores, symmetric) ------------------
// Upper-triangle tile pairs only; off-diagonal tiles are written twice
// (direct + transposed via smem bounce).
#define SYRK_LD  68
#define SYRK_SMEM (2 * 128 * SYRK_LD * 4)
#define TLDT 129

__global__ void __launch_bounds__(256, 2) final_syrk_kernel(
        const float* __restrict__ H, float* __restrict__ out) {
    extern __shared__ float smem[];
    float* As = smem;
    float* Bs = smem + 128 * SYRK_LD;
    int b = blockIdx.y;

    // map pair index -> (bi, bj), bi <= bj
    int r = blockIdx.x, bi = 0;
    while (r >= 16 - bi) { r -= 16 - bi; bi++; }
    int bj = bi + r;
    int i0 = bi * 128;
    int j0 = bj * 128;

    const float* Hb = H + (size_t)b * Nn * 64;
    int tid = threadIdx.x;

#pragma unroll
    for (int q = 0; q < 8; q++) {
        int f = q * 256 + tid;
        int rr = f >> 4;
        int c = (f & 15) * 4;
        float4 va = *(const float4*)&Hb[(size_t)(i0 + rr) * 64 + c];
        float4 vb = *(const float4*)&Hb[(size_t)(j0 + rr) * 64 + c];
        float4 ta, tb;
        ta.x = __uint_as_float(f2tf(va.x)); ta.y = __uint_as_float(f2tf(va.y));
        ta.z = __uint_as_float(f2tf(va.z)); ta.w = __uint_as_float(f2tf(va.w));
        tb.x = __uint_as_float(f2tf(vb.x)); tb.y = __uint_as_float(f2tf(vb.y));
        tb.z = __uint_as_float(f2tf(vb.z)); tb.w = __uint_as_float(f2tf(vb.w));
        *(float4*)&As[rr * SYRK_LD + c] = ta;
        *(float4*)&Bs[rr * SYRK_LD + c] = tb;
    }
    __syncthreads();

    int warp = tid >> 5, lane = tid & 31;
    int wm = warp & 3;
    int wn = warp >> 2;
    int g  = lane >> 2;
    int t  = lane & 3;

    float acc[2][8][4];
#pragma unroll
    for (int mt = 0; mt < 2; mt++)
#pragma unroll
        for (int nt = 0; nt < 8; nt++)
#pragma unroll
            for (int e = 0; e < 4; e++) acc[mt][nt][e] = 0.f;

#pragma unroll
    for (int ks = 0; ks < 8; ks++) {
        int k0 = ks * 8;
        uint32_t a[2][4], bf[8][2];
#pragma unroll
        for (int mt = 0; mt < 2; mt++) {
            int row = wm * 32 + mt * 16;
            a[mt][0] = __float_as_uint(As[(row + g    ) * SYRK_LD + k0 + t    ]);
            a[mt][1] = __float_as_uint(As[(row + g + 8) * SYRK_LD + k0 + t    ]);
            a[mt][2] = __float_as_uint(As[(row + g    ) * SYRK_LD + k0 + t + 4]);
            a[mt][3] = __float_as_uint(As[(row + g + 8) * SYRK_LD + k0 + t + 4]);
        }
#pragma unroll
        for (int nt = 0; nt < 8; nt++) {
            int col = wn * 64 + nt * 8;
            bf[nt][0] = __float_as_uint(Bs[(col + g) * SYRK_LD + k0 + t    ]);
            bf[nt][1] = __float_as_uint(Bs[(col + g) * SYRK_LD + k0 + t + 4]);
        }
#pragma unroll
        for (int mt = 0; mt < 2; mt++)
#pragma unroll
            for (int nt = 0; nt < 8; nt++) {
                asm volatile(
                    "mma.sync.aligned.m16n8k8.row.col.f32.tf32.tf32.f32 "
                    "{%0,%1,%2,%3}, {%4,%5,%6,%7}, {%8,%9}, {%0,%1,%2,%3};"
                    : "+f"(acc[mt][nt][0]), "+f"(acc[mt][nt][1]),
                      "+f"(acc[mt][nt][2]), "+f"(acc[mt][nt][3])
                    : "r"(a[mt][0]), "r"(a[mt][1]), "r"(a[mt][2]), "r"(a[mt][3]),
                      "r"(bf[nt][0]), "r"(bf[nt][1]));
            }
    }

    float* ob = out + (size_t)b * Nn * Nn;

    // direct write: tile rows i0.., cols j0..
#pragma unroll
    for (int mt = 0; mt < 2; mt++)
#pragma unroll
        for (int nt = 0; nt < 8; nt++) {
            int row = i0 + wm * 32 + mt * 16 + g;
            int col = j0 + wn * 64 + nt * 8 + 2 * t;
            float2 lo = make_float2(acc[mt][nt][0], acc[mt][nt][1]);
            float2 hi = make_float2(acc[mt][nt][2], acc[mt][nt][3]);
            *(float2*)&ob[(size_t)row * Nn + col]       = lo;
            *(float2*)&ob[(size_t)(row + 8) * Nn + col] = hi;
        }

    if (bi != bj) {
        // transposed write via smem bounce (reuse As/Bs space)
        __syncthreads();
        float* trans = smem;  // [128][TLDT]
#pragma unroll
        for (int mt = 0; mt < 2; mt++)
#pragma unroll
            for (int nt = 0; nt < 8; nt++) {
                int r0 = wm * 32 + mt * 16 + g;
                int c0 = wn * 64 + nt * 8 + 2 * t;
                trans[r0 * TLDT + c0]           = acc[mt][nt][0];
                trans[r0 * TLDT + c0 + 1]       = acc[mt][nt][1];
                trans[(r0 + 8) * TLDT + c0]     = acc[mt][nt][2];
                trans[(r0 + 8) * TLDT + c0 + 1] = acc[mt][nt][3];
            }
        __syncthreads();
        // warp w handles transposed rows jr = w*16 .. +15; coalesced STG.32
#pragma unroll 1
        for (int s = 0; s < 16; s++) {
            int jr = warp * 16 + s;
#pragma unroll
            for (int q = 0; q < 4; q++) {
                int ic = q * 32 + lane;
                float v = trans[ic * TLDT + jr];
                ob[(size_t)(j0 + jr) * Nn + i0 + ic] = v;
            }
        }
    }
}

// ---------------- launch ----------------------------------------------------
extern "C" void kernel_launch(void* const* d_in, const int* in_sizes, int n_in,
                              void* d_out, int out_size) {
    const float* x   = (const float*)d_in[0];
    const float* wr0 = (const float*)d_in[1];
    const float* wo0 = (const float*)d_in[2];
    const float* bb0 = (const float*)d_in[3];
    const float* wr1 = (const float*)d_in[4];
    const float* wo1 = (const float*)d_in[5];
    const float* bb1 = (const float*)d_in[6];
    const float* wr2 = (const float*)d_in[7];
    const float* wo2 = (const float*)d_in[8];
    const float* bb2 = (const float*)d_in[9];
    const float* wr3 = (const float*)d_in[10];
    const float* wo3 = (const float*)d_in[11];
    const float* bb3 = (const float*)d_in[12];
    float* out = (float*)d_out;

    float *acat0, *H, *h13, *h2;
    cudaGetSymbolAddress((void**)&acat0, g_h);
    cudaGetSymbolAddress((void**)&H,     g_hb);
    cudaGetSymbolAddress((void**)&h13,   g_a);
    cudaGetSymbolAddress((void**)&h2,    g_b);

    cudaFuncSetAttribute(final_syrk_kernel,
                         cudaFuncAttributeMaxDynamicSharedMemorySize, SYRK_SMEM);
    cudaFuncSetAttribute(gemm_fused_kernel,
                         cudaFuncAttributeMaxDynamicSharedMemorySize, FUSED_SMEM);

    // graph construction
    clear_deg_kernel<<<(BNT + 255) / 256, 256>>>();
    knn_kernel<<<BNT / 128, 128>>>(x);
    scan_kernel<<<1, 1024>>>();
    fill_kernel<<<(EDG + 255) / 256, 256>>>();

    // layer 0: Acat0 = [x | agg(x)] (K=20) -> h1 [BNT][128]
    aggx_kernel<<<BNT / 8, 256>>>(x, acat0);
    gemm_tf32_kernel<<<BNT / 128, 256>>>(acat0, 20, 20, 10, wo0, wr0, 128,
                                         bb0, h13, 128, 1);
    // layers 1-3: fused gather + GEMM
    gemm_fused_kernel<<<BNT / 128, 256, FUSED_SMEM>>>(h13, wo1, wr1, 128,
                                                      bb1, h2, 128, 1);
    gemm_fused_kernel<<<BNT / 128, 256, FUSED_SMEM>>>(h2, wo2, wr2, 128,
                                                      bb2, h13, 128, 1);
    gemm_fused_kernel<<<BNT / 128, 256, FUSED_SMEM>>>(h13, wo3, wr3, 64,
                                                      bb3, H, 64, 0);

    // final bilinear via tf32 tensor cores (symmetric: upper-triangle pairs)
    final_syrk_kernel<<<dim3(136, Bb), 256, SYRK_SMEM>>>(H, out);
}

// round 12
// speedup vs baseline: 2.0327x; 1.0824x over previous
#include <cuda_runtime.h>
#include <math_constants.h>
#include <cstdint>

#define Bb   16
#define Nn   2048
#define Cc   10
#define KK   16
#define BNT  (Bb*Nn)        // 32768 nodes
#define EDG  (BNT*KK)       // 524288 edges

// ---------------- scratch (device globals: no allocation allowed) ----------
__device__ int   g_nbr[EDG];
__device__ int   g_deg[BNT];
__device__ int   g_off[BNT];
__device__ int   g_cur[BNT];
__device__ int   g_rev[EDG];
__device__ float g_h [BNT*128];     // Acat0 (stride 20)
__device__ float g_hb[BNT*128];     // final H (stride 64)
__device__ float g_a [BNT*256];     // h1 / h3 (stride 128)
__device__ float g_b [BNT*256];     // h2 (stride 128)

// ---------------- kNN v3: 2 threads per query (parity-split candidates) ----
// Block = 256 threads covering 128 consecutive query points of one batch.
// Thread t handles query (t&127); half (t>>7) scans j-groups 8g + 4*half.
// Each half keeps its own 16-best; halves merged at the end (each half sees
// 1024 candidates >> 16, so both lists are full and the merge is exact).
__global__ void __launch_bounds__(256) knn_kernel(const float* __restrict__ x) {
    __shared__ float sn[Nn];
    __shared__ float sd[KK][256];
    __shared__ int   si[KK][256];
    int t    = threadIdx.x;
    int qi   = t & 127;
    int half = t >> 7;
    int node = blockIdx.x * 128 + qi;
    int b    = node >> 11;
    int i    = node & 2047;
    const float*  xb  = x + (size_t)b * Nn * Cc;
    const float4* xb4 = (const float4*)xb;

    for (int j = t; j < Nn; j += 256) {
        float s = 0.f;
#pragma unroll
        for (int c = 0; c < Cc; c++) { float v = xb[j * Cc + c]; s = fmaf(v, v, s); }
        sn[j] = s;
    }
    float xi[Cc];
#pragma unroll
    for (int c = 0; c < Cc; c++) xi[c] = xb[i * Cc + c];
#pragma unroll
    for (int r = 0; r < KK; r++) { sd[r][t] = CUDART_INF_F; si[r][t] = 0; }
    __syncthreads();
    float x2i = sn[i];

    float cut = CUDART_INF_F;
    int   cutpos = 0;

    for (int j0 = half * 4; j0 < Nn; j0 += 8) {
        float v[40];
#pragma unroll
        for (int q = 0; q < 10; q++) {
            float4 t4 = xb4[(j0 * 10) / 4 + q];
            v[q*4+0] = t4.x; v[q*4+1] = t4.y; v[q*4+2] = t4.z; v[q*4+3] = t4.w;
        }
#pragma unroll
        for (int jj = 0; jj < 4; jj++) {
            int j = j0 + jj;
            float dot = 0.f;
#pragma unroll
            for (int c = 0; c < Cc; c++) dot = fmaf(xi[c], v[jj * 10 + c], dot);
            float d2 = fmaf(-2.f, dot, x2i + sn[j]);
            if (j != i && d2 < cut) {
                sd[cutpos][t] = d2; si[cutpos][t] = j;
                float m = sd[0][t]; int mp = 0;
#pragma unroll
                for (int r = 1; r < KK; r++) {
                    float dr = sd[r][t];
                    if (dr > m) { m = dr; mp = r; }
                }
                cut = m; cutpos = mp;
            }
        }
    }
    __syncthreads();

    if (half == 0) {
        // merge partner's 16 into own list via same replace-max insert
#pragma unroll
        for (int r = 0; r < KK; r++) {
            float d2 = sd[r][t + 128];
            int   j  = si[r][t + 128];
            if (d2 < cut) {
                sd[cutpos][t] = d2; si[cutpos][t] = j;
                float m = sd[0][t]; int mp = 0;
#pragma unroll
                for (int rr = 1; rr < KK; rr++) {
                    float dr = sd[rr][t];
                    if (dr > m) { m = dr; mp = rr; }
                }
                cut = m; cutpos = mp;
            }
        }
        int base = node * KK;
#pragma unroll
        for (int r = 0; r < KK; r++) {
            int nb = (b << 11) + si[r][t];
            g_nbr[base + r] = nb;
            atomicAdd(&g_deg[nb], 1);
        }
    }
}

// ---------------- exclusive scan (shuffle-based, single block) --------------
__global__ void scan_kernel() {
    __shared__ int wsum[32];
    __shared__ int carry;
    int t = threadIdx.x, lane = t & 31, w = t >> 5;
    if (t == 0) carry = 0;
    __syncthreads();
    for (int c = 0; c < BNT / 1024; c++) {
        int idx = c * 1024 + t;
        int v = g_deg[idx];
        int inc = v;
#pragma unroll
        for (int o = 1; o < 32; o <<= 1) {
            int n = __shfl_up_sync(0xffffffffu, inc, o);
            if (lane >= o) inc += n;
        }
        if (lane == 31) wsum[w] = inc;
        __syncthreads();
        if (w == 0) {
            int s = wsum[lane];
#pragma unroll
            for (int o = 1; o < 32; o <<= 1) {
                int n = __shfl_up_sync(0xffffffffu, s, o);
                if (lane >= o) s += n;
            }
            wsum[lane] = s;
        }
        __syncthreads();
        int base = carry + ((w > 0) ? wsum[w - 1] : 0);
        int excl = base + inc - v;
        g_off[idx] = excl;
        g_cur[idx] = excl;
        __syncthreads();
        if (t == 1023) carry = carry + wsum[31];
        __syncthreads();
    }
}

__global__ void fill_kernel() {
    int e = blockIdx.x * blockDim.x + threadIdx.x;
    if (e >= EDG) return;
    int i = e >> 4;
    int v = g_nbr[e];
    int pos = atomicAdd(&g_cur[v], 1);
    g_rev[pos] = i;
}

// ---------------- layer-0 concat: Acat0[v] = [x_v (10) | sum x_u (10)] -----
__global__ void aggx_kernel(const float* __restrict__ x, float* __restrict__ acat) {
    int warp = threadIdx.x >> 5, lane = threadIdx.x & 31;
    int v = blockIdx.x * 8 + warp;
    float xv = 0.f;
    if (lane < 10) xv = x[(size_t)v * 10 + lane];
    int s = g_off[v];
    int e = s + g_deg[v];
    float a0 = 0.f, a1 = 0.f, a2 = 0.f, a3 = 0.f;
    int q = s;
    for (; q + 4 <= e; q += 4) {
        int u0 = __ldg(&g_rev[q]);
        int u1 = __ldg(&g_rev[q + 1]);
        int u2 = __ldg(&g_rev[q + 2]);
        int u3 = __ldg(&g_rev[q + 3]);
        if (lane < 10) {
            a0 += x[(size_t)u0 * 10 + lane];
            a1 += x[(size_t)u1 * 10 + lane];
            a2 += x[(size_t)u2 * 10 + lane];
            a3 += x[(size_t)u3 * 10 + lane];
        }
    }
    for (; q < e; q++) {
        int u = __ldg(&g_rev[q]);
        if (lane < 10) a0 += x[(size_t)u * 10 + lane];
    }
    float acc = (a0 + a1) + (a2 + a3);
    if (lane < 10) {
        acat[(size_t)v * 20 + lane]      = xv;
        acat[(size_t)v * 20 + 10 + lane] = acc;
    }
}

// ---------------- tf32 helpers ----------------------------------------------
__device__ __forceinline__ float f2tf_f(float f) {
    uint32_t u;
    asm("cvt.rna.tf32.f32 %0, %1;" : "=r"(u) : "f"(f));
    return __uint_as_float(u);
}
__device__ __forceinline__ uint32_t f2tf(float f) {
    uint32_t u;
    asm("cvt.rna.tf32.f32 %0, %1;" : "=r"(u) : "f"(f));
    return u;
}

#define GLDA 17

// ---------------- generic tf32 GEMM (layer 0): Out = relu(A@[wo;wr]+b) ------
__global__ void __launch_bounds__(256, 2) gemm_tf32_kernel(
        const float* __restrict__ A, int lda, int K, int Khalf,
        const float* __restrict__ wo, const float* __restrict__ wr, int P,
        const float* __restrict__ bias, float* __restrict__ Out, int ldo,
        int do_relu) {
    __shared__ float As[128 * GLDA];
    __shared__ float Ws[128 * GLDA];
    int bm  = blockIdx.x * 128;
    int tid = threadIdx.x;
    int r2  = tid >> 1;
    int kh  = (tid & 1) * 8;
    int warp = tid >> 5, lane = tid & 31;
    int wm = warp & 3, wn = warp >> 2;
    int g  = lane >> 2, t4 = lane & 3;

    float acc[2][8][4];
#pragma unroll
    for (int mt = 0; mt < 2; mt++)
#pragma unroll
        for (int nt = 0; nt < 8; nt++)
#pragma unroll
            for (int e = 0; e < 4; e++) acc[mt][nt][e] = 0.f;

    for (int k0 = 0; k0 < K; k0 += 16) {
        const float* Ap = &A[(size_t)(bm + r2) * lda + k0 + kh];
        if (k0 + kh + 8 <= K) {
            float4 v0 = *(const float4*)Ap;
            float4 v1 = *(const float4*)(Ap + 4);
            As[r2 * GLDA + kh + 0] = f2tf_f(v0.x);
            As[r2 * GLDA + kh + 1] = f2tf_f(v0.y);
            As[r2 * GLDA + kh + 2] = f2tf_f(v0.z);
            As[r2 * GLDA + kh + 3] = f2tf_f(v0.w);
            As[r2 * GLDA + kh + 4] = f2tf_f(v1.x);
            As[r2 * GLDA + kh + 5] = f2tf_f(v1.y);
            As[r2 * GLDA + kh + 6] = f2tf_f(v1.z);
            As[r2 * GLDA + kh + 7] = f2tf_f(v1.w);
        } else {
#pragma unroll
            for (int q = 0; q < 8; q++) {
                int kk = k0 + kh + q;
                As[r2 * GLDA + kh + q] = (kk < K) ? f2tf_f(Ap[q]) : 0.f;
            }
        }
#pragma unroll
        for (int q = 0; q < 8; q++) {
            int kk = k0 + kh + q;
            float v = 0.f;
            if (kk < K && r2 < P)
                v = (kk < Khalf) ? wo[(size_t)kk * P + r2]
                                 : wr[(size_t)(kk - Khalf) * P + r2];
            Ws[r2 * GLDA + kh + q] = f2tf_f(v);
        }
        __syncthreads();
#pragma unroll
        for (int ks = 0; ks < 16; ks += 8) {
            uint32_t a[2][4], bfr[8][2];
#pragma unroll
            for (int mt = 0; mt < 2; mt++) {
                int row = wm * 32 + mt * 16;
                a[mt][0] = __float_as_uint(As[(row + g    ) * GLDA + ks + t4    ]);
                a[mt][1] = __float_as_uint(As[(row + g + 8) * GLDA + ks + t4    ]);
                a[mt][2] = __float_as_uint(As[(row + g    ) * GLDA + ks + t4 + 4]);
                a[mt][3] = __float_as_uint(As[(row + g + 8) * GLDA + ks + t4 + 4]);
            }
#pragma unroll
            for (int nt = 0; nt < 8; nt++) {
                int col = wn * 64 + nt * 8;
                bfr[nt][0] = __float_as_uint(Ws[(col + g) * GLDA + ks + t4    ]);
                bfr[nt][1] = __float_as_uint(Ws[(col + g) * GLDA + ks + t4 + 4]);
            }
#pragma unroll
            for (int mt = 0; mt < 2; mt++)
#pragma unroll
                for (int nt = 0; nt < 8; nt++) {
                    asm volatile(
                        "mma.sync.aligned.m16n8k8.row.col.f32.tf32.tf32.f32 "
                        "{%0,%1,%2,%3}, {%4,%5,%6,%7}, {%8,%9}, {%0,%1,%2,%3};"
                        : "+f"(acc[mt][nt][0]), "+f"(acc[mt][nt][1]),
                          "+f"(acc[mt][nt][2]), "+f"(acc[mt][nt][3])
                        : "r"(a[mt][0]), "r"(a[mt][1]), "r"(a[mt][2]), "r"(a[mt][3]),
                          "r"(bfr[nt][0]), "r"(bfr[nt][1]));
                }
        }
        __syncthreads();
    }

#pragma unroll
    for (int nt = 0; nt < 8; nt++) {
        int col = wn * 64 + nt * 8 + 2 * t4;
        if (col >= P) continue;
        float b0 = bias[col], b1 = bias[col + 1];
#pragma unroll
        for (int mt = 0; mt < 2; mt++) {
            int row = bm + wm * 32 + mt * 16 + g;
            float o0 = acc[mt][nt][0] + b0;
            float o1 = acc[mt][nt][1] + b1;
            float o2 = acc[mt][nt][2] + b0;
            float o3 = acc[mt][nt][3] + b1;
            if (do_relu) {
                o0 = fmaxf(o0, 0.f); o1 = fmaxf(o1, 0.f);
                o2 = fmaxf(o2, 0.f); o3 = fmaxf(o3, 0.f);
            }
            *(float2*)&Out[(size_t)row * ldo + col]       = make_float2(o0, o1);
            *(float2*)&Out[(size_t)(row + 8) * ldo + col] = make_float2(o2, o3);
        }
    }
}

// ---------------- fused gather+GEMM (layers 1-3) -----------------------------
#define FLDT 132
#define FUSED_SMEM ((128 * FLDT + 2 * 128 * GLDA) * 4)

__global__ void __launch_bounds__(256, 2) gemm_fused_kernel(
        const float* __restrict__ h,
        const float* __restrict__ wo, const float* __restrict__ wr, int P,
        const float* __restrict__ bias, float* __restrict__ Out, int ldo,
        int do_relu) {
    extern __shared__ float sm[];
    float* agg = sm;                       // [128][FLDT]
    float* As  = sm + 128 * FLDT;          // [128][GLDA]
    float* Ws  = As + 128 * GLDA;          // [128][GLDA]
    int bm  = blockIdx.x * 128;
    int tid = threadIdx.x;
    int warp = tid >> 5, lane = tid & 31;

    // ---- gather neighbor sums, 4-way unrolled for MLP ----
#pragma unroll 1
    for (int s = 0; s < 16; s++) {
        int r = warp * 16 + s;
        int v = bm + r;
        int c4 = lane * 4;
        int off = g_off[v];
        int deg = g_deg[v];
        float4 a0 = make_float4(0.f, 0.f, 0.f, 0.f);
        float4 a1 = a0, a2 = a0, a3 = a0;
        int q = off, qe = off + deg;
        for (; q + 4 <= qe; q += 4) {
            int u0 = __ldg(&g_rev[q]);
            int u1 = __ldg(&g_rev[q + 1]);
            int u2 = __ldg(&g_rev[q + 2]);
            int u3 = __ldg(&g_rev[q + 3]);
            float4 t0 = *(const float4*)&h[(size_t)u0 * 128 + c4];
            float4 t1 = *(const float4*)&h[(size_t)u1 * 128 + c4];
            float4 t2 = *(const float4*)&h[(size_t)u2 * 128 + c4];
            float4 t3 = *(const float4*)&h[(size_t)u3 * 128 + c4];
            a0.x += t0.x; a0.y += t0.y; a0.z += t0.z; a0.w += t0.w;
            a1.x += t1.x; a1.y += t1.y; a1.z += t1.z; a1.w += t1.w;
            a2.x += t2.x; a2.y += t2.y; a2.z += t2.z; a2.w += t2.w;
            a3.x += t3.x; a3.y += t3.y; a3.z += t3.z; a3.w += t3.w;
        }
        for (; q < qe; q++) {
            int u = __ldg(&g_rev[q]);
            float4 t0 = *(const float4*)&h[(size_t)u * 128 + c4];
            a0.x += t0.x; a0.y += t0.y; a0.z += t0.z; a0.w += t0.w;
        }
        float4 acc;
        acc.x = (a0.x + a1.x) + (a2.x + a3.x);
        acc.y = (a0.y + a1.y) + (a2.y + a3.y);
        acc.z = (a0.z + a1.z) + (a2.z + a3.z);
        acc.w = (a0.w + a1.w) + (a2.w + a3.w);
        float4 ta;
        ta.x = f2tf_f(acc.x); ta.y = f2tf_f(acc.y);
        ta.z = f2tf_f(acc.z); ta.w = f2tf_f(acc.w);
        *(float4*)&agg[r * FLDT + c4] = ta;
    }
    __syncthreads();

    int r2 = tid >> 1;
    int kh = (tid & 1) * 8;
    int wm = warp & 3, wn = warp >> 2;
    int g  = lane >> 2, t4 = lane & 3;

    float acc[2][8][4];
#pragma unroll
    for (int mt = 0; mt < 2; mt++)
#pragma unroll
        for (int nt = 0; nt < 8; nt++)
#pragma unroll
            for (int e = 0; e < 4; e++) acc[mt][nt][e] = 0.f;

    // ---- left K-half: root features from global h (staged) ----
    for (int k0 = 0; k0 < 128; k0 += 16) {
        const float* Ap = &h[(size_t)(bm + r2) * 128 + k0 + kh];
        float4 v0 = *(const float4*)Ap;
        float4 v1 = *(const float4*)(Ap + 4);
        As[r2 * GLDA + kh + 0] = f2tf_f(v0.x);
        As[r2 * GLDA + kh + 1] = f2tf_f(v0.y);
        As[r2 * GLDA + kh + 2] = f2tf_f(v0.z);
        As[r2 * GLDA + kh + 3] = f2tf_f(v0.w);
        As[r2 * GLDA + kh + 4] = f2tf_f(v1.x);
        As[r2 * GLDA + kh + 5] = f2tf_f(v1.y);
        As[r2 * GLDA + kh + 6] = f2tf_f(v1.z);
        As[r2 * GLDA + kh + 7] = f2tf_f(v1.w);
#pragma unroll
        for (int q = 0; q < 8; q++) {
            int kk = k0 + kh + q;
            float v = (r2 < P) ? wo[(size_t)kk * P + r2] : 0.f;
            Ws[r2 * GLDA + kh + q] = f2tf_f(v);
        }
        __syncthreads();
#pragma unroll
        for (int ks = 0; ks < 16; ks += 8) {
            uint32_t a[2][4], bfr[8][2];
#pragma unroll
            for (int mt = 0; mt < 2; mt++) {
                int row = wm * 32 + mt * 16;
                a[mt][0] = __float_as_uint(As[(row + g    ) * GLDA + ks + t4    ]);
                a[mt][1] = __float_as_uint(As[(row + g + 8) * GLDA + ks + t4    ]);
                a[mt][2] = __float_as_uint(As[(row + g    ) * GLDA + ks + t4 + 4]);
                a[mt][3] = __float_as_uint(As[(row + g + 8) * GLDA + ks + t4 + 4]);
            }
#pragma unroll
            for (int nt = 0; nt < 8; nt++) {
                int col = wn * 64 + nt * 8;
                bfr[nt][0] = __float_as_uint(Ws[(col + g) * GLDA + ks + t4    ]);
                bfr[nt][1] = __float_as_uint(Ws[(col + g) * GLDA + ks + t4 + 4]);
            }
#pragma unroll
            for (int mt = 0; mt < 2; mt++)
#pragma unroll
                for (int nt = 0; nt < 8; nt++) {
                    asm volatile(
                        "mma.sync.aligned.m16n8k8.row.col.f32.tf32.tf32.f32 "
                        "{%0,%1,%2,%3}, {%4,%5,%6,%7}, {%8,%9}, {%0,%1,%2,%3};"
                        : "+f"(acc[mt][nt][0]), "+f"(acc[mt][nt][1]),
                          "+f"(acc[mt][nt][2]), "+f"(acc[mt][nt][3])
                        : "r"(a[mt][0]), "r"(a[mt][1]), "r"(a[mt][2]), "r"(a[mt][3]),
                          "r"(bfr[nt][0]), "r"(bfr[nt][1]));
                }
        }
        __syncthreads();
    }

    // ---- right K-half: aggregated features from smem (direct fragments) ----
    for (int k0 = 0; k0 < 128; k0 += 16) {
#pragma unroll
        for (int q = 0; q < 8; q++) {
            int kk = k0 + kh + q;
            float v = (r2 < P) ? wr[(size_t)kk * P + r2] : 0.f;
            Ws[r2 * GLDA + kh + q] = f2tf_f(v);
        }
        __syncthreads();
#pragma unroll
        for (int ks = 0; ks < 16; ks += 8) {
            int kb = k0 + ks;
            uint32_t a[2][4], bfr[8][2];
#pragma unroll
            for (int mt = 0; mt < 2; mt++) {
                int row = wm * 32 + mt * 16;
                a[mt][0] = __float_as_uint(agg[(row + g    ) * FLDT + kb + t4    ]);
                a[mt][1] = __float_as_uint(agg[(row + g + 8) * FLDT + kb + t4    ]);
                a[mt][2] = __float_as_uint(agg[(row + g    ) * FLDT + kb + t4 + 4]);
                a[mt][3] = __float_as_uint(agg[(row + g + 8) * FLDT + kb + t4 + 4]);
            }
#pragma unroll
            for (int nt = 0; nt < 8; nt++) {
                int col = wn * 64 + nt * 8;
                bfr[nt][0] = __float_as_uint(Ws[(col + g) * GLDA + ks + t4    ]);
                bfr[nt][1] = __float_as_uint(Ws[(col + g) * GLDA + ks + t4 + 4]);
            }
#pragma unroll
            for (int mt = 0; mt < 2; mt++)
#pragma unroll
                for (int nt = 0; nt < 8; nt++) {
                    asm volatile(
                        "mma.sync.aligned.m16n8k8.row.col.f32.tf32.tf32.f32 "
                        "{%0,%1,%2,%3}, {%4,%5,%6,%7}, {%8,%9}, {%0,%1,%2,%3};"
                        : "+f"(acc[mt][nt][0]), "+f"(acc[mt][nt][1]),
                          "+f"(acc[mt][nt][2]), "+f"(acc[mt][nt][3])
                        : "r"(a[mt][0]), "r"(a[mt][1]), "r"(a[mt][2]), "r"(a[mt][3]),
                          "r"(bfr[nt][0]), "r"(bfr[nt][1]));
                }
        }
        __syncthreads();
    }

    // ---- epilogue: bias + optional relu ----
#pragma unroll
    for (int nt = 0; nt < 8; nt++) {
        int col = wn * 64 + nt * 8 + 2 * t4;
        if (col >= P) continue;
        float b0 = bias[col], b1 = bias[col + 1];
#pragma unroll
        for (int mt = 0; mt < 2; mt++) {
            int row = bm + wm * 32 + mt * 16 + g;
            float o0 = acc[mt][nt][0] + b0;
            float o1 = acc[mt][nt][1] + b1;
            float o2 = acc[mt][nt][2] + b0;
            float o3 = acc[mt][nt][3] + b1;
            if (do_relu) {
                o0 = fmaxf(o0, 0.f); o1 = fmaxf(o1, 0.f);
                o2 = fmaxf(o2, 0.f); o3 = fmaxf(o3, 0.f);
            }
            *(float2*)&Out[(size_t)row * ldo + col]       = make_float2(o0, o1);
            *(float2*)&Out[(size_t)(row + 8) * ldo + col] = make_float2(o2, o3);
        }
    }
}

// ---------------- final syrk (tf32 tensor cores, symmetric) ------------------
#define SYRK_LD  68
#define SYRK_SMEM (2 * 128 * SYRK_LD * 4)
#define TLDT 129

__global__ void __launch_bounds__(256, 2) final_syrk_kernel(
        const float* __restrict__ H, float* __restrict__ out) {
    extern __shared__ float smem[];
    float* As = smem;
    float* Bs = smem + 128 * SYRK_LD;
    int b = blockIdx.y;

    int r = blockIdx.x, bi = 0;
    while (r >= 16 - bi) { r -= 16 - bi; bi++; }
    int bj = bi + r;
    int i0 = bi * 128;
    int j0 = bj * 128;

    const float* Hb = H + (size_t)b * Nn * 64;
    int tid = threadIdx.x;

#pragma unroll
    for (int q = 0; q < 8; q++) {
        int f = q * 256 + tid;
        int rr = f >> 4;
        int c = (f & 15) * 4;
        float4 va = *(const float4*)&Hb[(size_t)(i0 + rr) * 64 + c];
        float4 vb = *(const float4*)&Hb[(size_t)(j0 + rr) * 64 + c];
        float4 ta, tb;
        ta.x = __uint_as_float(f2tf(va.x)); ta.y = __uint_as_float(f2tf(va.y));
        ta.z = __uint_as_float(f2tf(va.z)); ta.w = __uint_as_float(f2tf(va.w));
        tb.x = __uint_as_float(f2tf(vb.x)); tb.y = __uint_as_float(f2tf(vb.y));
        tb.z = __uint_as_float(f2tf(vb.z)); tb.w = __uint_as_float(f2tf(vb.w));
        *(float4*)&As[rr * SYRK_LD + c] = ta;
        *(float4*)&Bs[rr * SYRK_LD + c] = tb;
    }
    __syncthreads();

    int warp = tid >> 5, lane = tid & 31;
    int wm = warp & 3;
    int wn = warp >> 2;
    int g  = lane >> 2;
    int t  = lane & 3;

    float acc[2][8][4];
#pragma unroll
    for (int mt = 0; mt < 2; mt++)
#pragma unroll
        for (int nt = 0; nt < 8; nt++)
#pragma unroll
            for (int e = 0; e < 4; e++) acc[mt][nt][e] = 0.f;

#pragma unroll
    for (int ks = 0; ks < 8; ks++) {
        int k0 = ks * 8;
        uint32_t a[2][4], bf[8][2];
#pragma unroll
        for (int mt = 0; mt < 2; mt++) {
            int row = wm * 32 + mt * 16;
            a[mt][0] = __float_as_uint(As[(row + g    ) * SYRK_LD + k0 + t    ]);
            a[mt][1] = __float_as_uint(As[(row + g + 8) * SYRK_LD + k0 + t    ]);
            a[mt][2] = __float_as_uint(As[(row + g    ) * SYRK_LD + k0 + t + 4]);
            a[mt][3] = __float_as_uint(As[(row + g + 8) * SYRK_LD + k0 + t + 4]);
        }
#pragma unroll
        for (int nt = 0; nt < 8; nt++) {
            int col = wn * 64 + nt * 8;
            bf[nt][0] = __float_as_uint(Bs[(col + g) * SYRK_LD + k0 + t    ]);
            bf[nt][1] = __float_as_uint(Bs[(col + g) * SYRK_LD + k0 + t + 4]);
        }
#pragma unroll
        for (int mt = 0; mt < 2; mt++)
#pragma unroll
            for (int nt = 0; nt < 8; nt++) {
                asm volatile(
                    "mma.sync.aligned.m16n8k8.row.col.f32.tf32.tf32.f32 "
                    "{%0,%1,%2,%3}, {%4,%5,%6,%7}, {%8,%9}, {%0,%1,%2,%3};"
                    : "+f"(acc[mt][nt][0]), "+f"(acc[mt][nt][1]),
                      "+f"(acc[mt][nt][2]), "+f"(acc[mt][nt][3])
                    : "r"(a[mt][0]), "r"(a[mt][1]), "r"(a[mt][2]), "r"(a[mt][3]),
                      "r"(bf[nt][0]), "r"(bf[nt][1]));
            }
    }

    float* ob = out + (size_t)b * Nn * Nn;

#pragma unroll
    for (int mt = 0; mt < 2; mt++)
#pragma unroll
        for (int nt = 0; nt < 8; nt++) {
            int row = i0 + wm * 32 + mt * 16 + g;
            int col = j0 + wn * 64 + nt * 8 + 2 * t;
            float2 lo = make_float2(acc[mt][nt][0], acc[mt][nt][1]);
            float2 hi = make_float2(acc[mt][nt][2], acc[mt][nt][3]);
            *(float2*)&ob[(size_t)row * Nn + col]       = lo;
            *(float2*)&ob[(size_t)(row + 8) * Nn + col] = hi;
        }

    if (bi != bj) {
        __syncthreads();
        float* trans = smem;  // [128][TLDT]
#pragma unroll
        for (int mt = 0; mt < 2; mt++)
#pragma unroll
            for (int nt = 0; nt < 8; nt++) {
                int r0 = wm * 32 + mt * 16 + g;
                int c0 = wn * 64 + nt * 8 + 2 * t;
                trans[r0 * TLDT + c0]           = acc[mt][nt][0];
                trans[r0 * TLDT + c0 + 1]       = acc[mt][nt][1];
                trans[(r0 + 8) * TLDT + c0]     = acc[mt][nt][2];
                trans[(r0 + 8) * TLDT + c0 + 1] = acc[mt][nt][3];
            }
        __syncthreads();
#pragma unroll 1
        for (int s = 0; s < 16; s++) {
            int jr = warp * 16 + s;
#pragma unroll
            for (int q = 0; q < 4; q++) {
                int ic = q * 32 + lane;
                float v = trans[ic * TLDT + jr];
                ob[(size_t)(j0 + jr) * Nn + i0 + ic] = v;
            }
        }
    }
}

// ---------------- launch ----------------------------------------------------
extern "C" void kernel_launch(void* const* d_in, const int* in_sizes, int n_in,
                              void* d_out, int out_size) {
    const float* x   = (const float*)d_in[0];
    const float* wr0 = (const float*)d_in[1];
    const float* wo0 = (const float*)d_in[2];
    const float* bb0 = (const float*)d_in[3];
    const float* wr1 = (const float*)d_in[4];
    const float* wo1 = (const float*)d_in[5];
    const float* bb1 = (const float*)d_in[6];
    const float* wr2 = (const float*)d_in[7];
    const float* wo2 = (const float*)d_in[8];
    const float* bb2 = (const float*)d_in[9];
    const float* wr3 = (const float*)d_in[10];
    const float* wo3 = (const float*)d_in[11];
    const float* bb3 = (const float*)d_in[12];
    float* out = (float*)d_out;

    float *acat0, *H, *h13, *h2;
    int *degp;
    cudaGetSymbolAddress((void**)&acat0, g_h);
    cudaGetSymbolAddress((void**)&H,     g_hb);
    cudaGetSymbolAddress((void**)&h13,   g_a);
    cudaGetSymbolAddress((void**)&h2,    g_b);
    cudaGetSymbolAddress((void**)&degp,  g_deg);

    cudaFuncSetAttribute(final_syrk_kernel,
                         cudaFuncAttributeMaxDynamicSharedMemorySize, SYRK_SMEM);
    cudaFuncSetAttribute(gemm_fused_kernel,
                         cudaFuncAttributeMaxDynamicSharedMemorySize, FUSED_SMEM);

    // graph construction
    cudaMemsetAsync(degp, 0, BNT * sizeof(int), 0);
    knn_kernel<<<BNT / 128, 256>>>(x);
    scan_kernel<<<1, 1024>>>();
    fill_kernel<<<(EDG + 255) / 256, 256>>>();

    // layer 0: Acat0 = [x | agg(x)] (K=20) -> h1 [BNT][128]
    aggx_kernel<<<BNT / 8, 256>>>(x, acat0);
    gemm_tf32_kernel<<<BNT / 128, 256>>>(acat0, 20, 20, 10, wo0, wr0, 128,
                                         bb0, h13, 128, 1);
    // layers 1-3: fused gather + GEMM
    gemm_fused_kernel<<<BNT / 128, 256, FUSED_SMEM>>>(h13, wo1, wr1, 128,
                                                      bb1, h2, 128, 1);
    gemm_fused_kernel<<<BNT / 128, 256, FUSED_SMEM>>>(h2, wo2, wr2, 128,
                                                      bb2, h13, 128, 1);
    gemm_fused_kernel<<<BNT / 128, 256, FUSED_SMEM>>>(h13, wo3, wr3, 64,
                                                      bb3, H, 64, 0);

    // final bilinear via tf32 tensor cores (symmetric: upper-triangle pairs)
    final_syrk_kernel<<<dim3(136, Bb), 256, SYRK_SMEM>>>(H, out);
}